// round 5
// baseline (speedup 1.0000x reference)
#include <cuda_runtime.h>
#include <math.h>

#define NMAX 50000
#define EMAX 800000
#define ETMAX (NMAX + EMAX)
#define BMAX 512

// ---------------- scratch (device globals; no allocations allowed) ----------
__device__ float g_xl[NMAX * 128];
__device__ float g_xr[NMAX * 128];
__device__ float g_h[NMAX * 128];
__device__ float g_agg[NMAX * 128];
__device__ float g_logits[ETMAX * 4];
__device__ float g_lmax[NMAX * 4];
__device__ float g_denom[NMAX * 4];
__device__ int   g_src[ETMAX];
__device__ int   g_dst[ETMAX];
__device__ int   g_batch[NMAX];
__device__ float g_pool[BMAX * 32];
__device__ float g_cnt[BMAX];
__device__ int   g_is64;

// ---------------- helpers ---------------------------------------------------
__device__ __forceinline__ void atomicMaxF(float* addr, float val) {
    int old = __float_as_int(*addr);
    while (__int_as_float(old) < val) {
        int assumed = old;
        old = atomicCAS((int*)addr, assumed, __float_as_int(val));
        if (old == assumed) break;
    }
}

// ---------------- dtype sniff: int64 vs int32 edge_index --------------------
// If int64: high words (odd int32 indices) of the first 256 elements are all 0
// (values are node ids in [0, 50000)). If int32, those words are random node
// ids -> OR is nonzero with certainty.
__global__ void detect_kernel(const void* ei) {
    __shared__ int s;
    if (threadIdx.x == 0) s = 0;
    __syncthreads();
    const int* w = (const int*)ei;
    int v = w[2 * threadIdx.x + 1];
    atomicOr(&s, v);
    __syncthreads();
    if (threadIdx.x == 0) g_is64 = (s == 0) ? 1 : 0;
}

// Convert edge_index (+ append self loops) and batch to int32.
__global__ void convert_kernel(const void* ei, const void* batch, int E, int N) {
    int i = blockIdx.x * blockDim.x + threadIdx.x;
    int is64 = g_is64;
    if (i < E) {
        int s, d;
        if (is64) {
            const long long* p = (const long long*)ei;
            s = (int)p[i]; d = (int)p[(long long)E + i];
        } else {
            const int* p = (const int*)ei;
            s = p[i]; d = p[E + i];
        }
        g_src[i] = s; g_dst[i] = d;
    } else if (i < E + N) {
        int n = i - E;
        g_src[i] = n; g_dst[i] = n;
    }
    if (i < N) {
        g_batch[i] = is64 ? (int)((const long long*)batch)[i]
                          : ((const int*)batch)[i];
    }
}

// ---------------- GEMM: Y[N,DOUT] = X[N,128] @ W[128,DOUT] + b --------------
// Block = DOUT threads, 8 nodes per block. X rows staged in shared; W column
// element loaded once per k and reused for 8 nodes (broadcast LDS for X).
template <int DOUT>
__global__ void gemm_bias_kernel(const float* __restrict__ X,
                                 const float* __restrict__ W,
                                 const float* __restrict__ b,
                                 float* __restrict__ Y, int N) {
    __shared__ float sh[8 * 128];
    int n0 = blockIdx.x * 8;
    int tid = threadIdx.x;
    for (int idx = tid; idx < 8 * 128; idx += DOUT) {
        int r = idx >> 7, c = idx & 127;
        int n = n0 + r;
        sh[idx] = (n < N) ? X[n * 128 + c] : 0.f;
    }
    __syncthreads();
    float acc[8];
#pragma unroll
    for (int r = 0; r < 8; r++) acc[r] = 0.f;
    for (int k = 0; k < 128; k++) {
        float w = W[k * DOUT + tid];
#pragma unroll
        for (int r = 0; r < 8; r++) acc[r] += sh[r * 128 + k] * w;
    }
    float bb = b[tid];
#pragma unroll
    for (int r = 0; r < 8; r++) {
        int n = n0 + r;
        if (n < N) Y[n * DOUT + tid] = acc[r] + bb;
    }
}

// ---------------- per-layer init --------------------------------------------
__global__ void init_layer_kernel(int N, int H, int DOUT) {
    int i = blockIdx.x * blockDim.x + threadIdx.x;
    if (i < N * H) {
        g_lmax[i] = __int_as_float(0xff800000);  // -inf
        g_denom[i] = 0.f;
    }
    if (i < N * DOUT) g_agg[i] = 0.f;
}

// ---------------- edge: logits + segment max --------------------------------
// Warp per edge. Lane l owns channel l of each head. Full butterfly reduce
// leaves every head-sum in all lanes; lane h commits head h.
template <int H>
__global__ void edge_logits_kernel(const float* __restrict__ att, int ET) {
    int w = (blockIdx.x * blockDim.x + threadIdx.x) >> 5;
    int lane = threadIdx.x & 31;
    if (w >= ET) return;
    int s = g_src[w], d = g_dst[w];
    const float* pl = g_xl + (size_t)s * (H * 32);
    const float* pr = g_xr + (size_t)d * (H * 32);
    float part[H];
#pragma unroll
    for (int h = 0; h < H; h++) {
        float m = pl[h * 32 + lane] + pr[h * 32 + lane];
        m = m > 0.f ? m : 0.2f * m;
        part[h] = m * __ldg(att + h * 32 + lane);
    }
#pragma unroll
    for (int h = 0; h < H; h++)
#pragma unroll
        for (int off = 16; off; off >>= 1)
            part[h] += __shfl_xor_sync(0xffffffffu, part[h], off);
    if (lane < H) {
        float v = part[lane];
        g_logits[w * H + lane] = v;
        atomicMaxF(&g_lmax[d * H + lane], v);
    }
}

// ---------------- edge: exp + segment sum -----------------------------------
template <int H>
__global__ void edge_exp_kernel(int ET) {
    int i = blockIdx.x * blockDim.x + threadIdx.x;
    if (i >= ET * H) return;
    int e = i / H;
    int h = i - e * H;
    int d = g_dst[e];
    float t = __expf(g_logits[i] - g_lmax[d * H + h]);
    g_logits[i] = t;
    atomicAdd(&g_denom[d * H + h], t);
}

// ---------------- denom -> reciprocal (hoists E*H divisions to N*H) ---------
__global__ void recip_denom_kernel(int NH) {
    int i = blockIdx.x * blockDim.x + threadIdx.x;
    if (i < NH) g_denom[i] = 1.f / (g_denom[i] + 1e-16f);
}

// ---------------- edge: weighted aggregate ----------------------------------
template <int H>
__global__ void edge_agg_kernel(int ET) {
    int w = (blockIdx.x * blockDim.x + threadIdx.x) >> 5;
    int lane = threadIdx.x & 31;
    if (w >= ET) return;
    int s = g_src[w], d = g_dst[w];
    float a = 0.f;
    if (lane < H)
        a = g_logits[w * H + lane] * g_denom[d * H + lane];
#pragma unroll
    for (int h = 0; h < H; h++) {
        float alpha = __shfl_sync(0xffffffffu, a, h);
        atomicAdd(&g_agg[(size_t)d * (H * 32) + h * 32 + lane],
                  alpha * g_xl[(size_t)s * (H * 32) + h * 32 + lane]);
    }
}

// ---------------- bias + ELU ------------------------------------------------
__global__ void bias_elu_kernel(const float* __restrict__ b, int N, int DOUT) {
    int i = blockIdx.x * blockDim.x + threadIdx.x;
    if (i >= N * DOUT) return;
    int j = i & (DOUT - 1);
    float v = g_agg[i] + b[j];
    g_h[i] = v > 0.f ? v : expm1f(v);
}

// ---------------- pooling ---------------------------------------------------
__global__ void pool_init_kernel(int B) {
    int i = blockIdx.x * blockDim.x + threadIdx.x;
    if (i < B * 32) g_pool[i] = 0.f;
    if (i < B) g_cnt[i] = 0.f;
}

__global__ void pool_kernel(int N) {
    int i = blockIdx.x * blockDim.x + threadIdx.x;
    if (i >= N * 32) return;
    int n = i >> 5, c = i & 31;
    int b = g_batch[n];
    atomicAdd(&g_pool[b * 32 + c], g_h[n * 32 + c]);
    if (c == 0) atomicAdd(&g_cnt[b], 1.f);
}

// ---------------- MLP head --------------------------------------------------
// Warp per graph: lane j = hidden unit j; then warp-reduce the final dot.
__global__ void head_kernel(const float* __restrict__ meta,
                            const float* __restrict__ Wh1,
                            const float* __restrict__ bh1,
                            const float* __restrict__ Wh2,
                            const float* __restrict__ bh2,
                            float* __restrict__ out, int B) {
    int g = (blockIdx.x * blockDim.x + threadIdx.x) >> 5;
    int lane = threadIdx.x & 31;
    if (g >= B) return;
    float c = g_cnt[g];
    if (c < 1.f) c = 1.f;
    float inv = 1.f / c;
    float acc = bh1[lane];
    for (int k = 0; k < 32; k++)
        acc += g_pool[g * 32 + k] * inv * Wh1[k * 32 + lane];
    for (int k = 0; k < 12; k++)
        acc += meta[g * 12 + k] * Wh1[(32 + k) * 32 + lane];
    acc = acc > 0.f ? acc : 0.f;
    float r = acc * Wh2[lane];
#pragma unroll
    for (int off = 16; off; off >>= 1)
        r += __shfl_xor_sync(0xffffffffu, r, off);
    if (lane == 0) out[g] = r + bh2[0];
}

// ---------------- host ------------------------------------------------------
extern "C" void kernel_launch(void* const* d_in, const int* in_sizes, int n_in,
                              void* d_out, int out_size) {
    const float* x     = (const float*)d_in[0];
    const void*  ei    = d_in[1];
    const void*  batch = d_in[2];
    const float* meta  = (const float*)d_in[3];

    const float *Wl[3], *bl[3], *Wr[3], *br[3], *att[3], *bo[3];
    for (int l = 0; l < 3; l++) {
        int base = 4 + 6 * l;
        Wl[l]  = (const float*)d_in[base + 0];
        bl[l]  = (const float*)d_in[base + 1];
        Wr[l]  = (const float*)d_in[base + 2];
        br[l]  = (const float*)d_in[base + 3];
        att[l] = (const float*)d_in[base + 4];
        bo[l]  = (const float*)d_in[base + 5];
    }
    const float* Wh1 = (const float*)d_in[22];
    const float* bh1 = (const float*)d_in[23];
    const float* Wh2 = (const float*)d_in[24];
    const float* bh2 = (const float*)d_in[25];

    int N = in_sizes[0] / 128;
    int E = in_sizes[1] / 2;
    int ET = E + N;
    int B = in_sizes[3] / 12;
    float* out = (float*)d_out;

    float *p_xl, *p_xr, *p_h;
    cudaGetSymbolAddress((void**)&p_xl, g_xl);
    cudaGetSymbolAddress((void**)&p_xr, g_xr);
    cudaGetSymbolAddress((void**)&p_h, g_h);

    detect_kernel<<<1, 256>>>(ei);
    convert_kernel<<<(ET + 255) / 256, 256>>>(ei, batch, E, N);

    int gemm_blocks = (N + 7) / 8;
    int edge_warp_blocks = (ET * 32 + 255) / 256;

    // ---- layers 0 and 1: H=4, DOUT=128 ----
    for (int l = 0; l < 2; l++) {
        const float* X = (l == 0) ? x : p_h;
        gemm_bias_kernel<128><<<gemm_blocks, 128>>>(X, Wl[l], bl[l], p_xl, N);
        gemm_bias_kernel<128><<<gemm_blocks, 128>>>(X, Wr[l], br[l], p_xr, N);
        init_layer_kernel<<<(N * 128 + 255) / 256, 256>>>(N, 4, 128);
        edge_logits_kernel<4><<<edge_warp_blocks, 256>>>(att[l], ET);
        edge_exp_kernel<4><<<(ET * 4 + 255) / 256, 256>>>(ET);
        recip_denom_kernel<<<(N * 4 + 255) / 256, 256>>>(N * 4);
        edge_agg_kernel<4><<<edge_warp_blocks, 256>>>(ET);
        bias_elu_kernel<<<(N * 128 + 255) / 256, 256>>>(bo[l], N, 128);
    }

    // ---- layer 2: H=1, DOUT=32 ----
    gemm_bias_kernel<32><<<gemm_blocks, 32>>>(p_h, Wl[2], bl[2], p_xl, N);
    gemm_bias_kernel<32><<<gemm_blocks, 32>>>(p_h, Wr[2], br[2], p_xr, N);
    init_layer_kernel<<<(N * 32 + 255) / 256, 256>>>(N, 1, 32);
    edge_logits_kernel<1><<<edge_warp_blocks, 256>>>(att[2], ET);
    edge_exp_kernel<1><<<(ET + 255) / 256, 256>>>(ET);
    recip_denom_kernel<<<(N + 255) / 256, 256>>>(N);
    edge_agg_kernel<1><<<edge_warp_blocks, 256>>>(ET);
    bias_elu_kernel<<<(N * 32 + 255) / 256, 256>>>(bo[2], N, 32);

    // ---- pool + head ----
    pool_init_kernel<<<(B * 32 + 255) / 256, 256>>>(B);
    pool_kernel<<<(N * 32 + 255) / 256, 256>>>(N);
    head_kernel<<<(B * 32 + 255) / 256, 256>>>(meta, Wh1, bh1, Wh2, bh2, out, B);
}

// round 6
// speedup vs baseline: 1.8053x; 1.8053x over previous
#include <cuda_runtime.h>
#include <math.h>

#define NMAX 50000
#define EMAX 800000
#define ETMAX (NMAX + EMAX)
#define BMAX 512
#define SCAN_BLK 256

// ---------------- scratch (device globals; no allocations allowed) ----------
__device__ float g_xl[NMAX * 128];
__device__ float g_xr[NMAX * 128];
__device__ float g_h[NMAX * 128];
__device__ int   g_src[ETMAX];
__device__ int   g_dst[ETMAX];
__device__ int   g_csrc[ETMAX];      // src node per dst-sorted edge
__device__ int   g_deg[NMAX];
__device__ int   g_scan[NMAX];
__device__ int   g_bsum[SCAN_BLK];
__device__ int   g_rowptr[NMAX + 1];
__device__ int   g_cursor[NMAX];
__device__ int   g_batch[NMAX];
__device__ float g_pool[BMAX * 32];
__device__ float g_cnt[BMAX];
__device__ int   g_is64;

// ---------------- dtype sniff: int64 vs int32 edge_index --------------------
__global__ void detect_kernel(const void* ei) {
    __shared__ int s;
    if (threadIdx.x == 0) s = 0;
    __syncthreads();
    const int* w = (const int*)ei;
    int v = w[2 * threadIdx.x + 1];
    atomicOr(&s, v);
    __syncthreads();
    if (threadIdx.x == 0) g_is64 = (s == 0) ? 1 : 0;
}

// Convert edge_index (+ self loops) and batch to int32; zero degree counters.
__global__ void convert_kernel(const void* ei, const void* batch, int E, int N) {
    int i = blockIdx.x * blockDim.x + threadIdx.x;
    int is64 = g_is64;
    if (i < E) {
        int s, d;
        if (is64) {
            const long long* p = (const long long*)ei;
            s = (int)p[i]; d = (int)p[(long long)E + i];
        } else {
            const int* p = (const int*)ei;
            s = p[i]; d = p[E + i];
        }
        g_src[i] = s; g_dst[i] = d;
    } else if (i < E + N) {
        int n = i - E;
        g_src[i] = n; g_dst[i] = n;
    }
    if (i < N) {
        g_batch[i] = is64 ? (int)((const long long*)batch)[i]
                          : ((const int*)batch)[i];
        g_deg[i] = 0;
    }
}

// ---------------- CSR build: histogram -> scan -> scatter -------------------
__global__ void hist_kernel(int ET) {
    int i = blockIdx.x * blockDim.x + threadIdx.x;
    if (i < ET) atomicAdd(&g_deg[g_dst[i]], 1);
}

__global__ void scan1_kernel(int N) {
    __shared__ int sh[SCAN_BLK];
    int i = blockIdx.x * SCAN_BLK + threadIdx.x;
    int v = (i < N) ? g_deg[i] : 0;
    sh[threadIdx.x] = v;
    __syncthreads();
    for (int off = 1; off < SCAN_BLK; off <<= 1) {
        int t = (threadIdx.x >= off) ? sh[threadIdx.x - off] : 0;
        __syncthreads();
        sh[threadIdx.x] += t;
        __syncthreads();
    }
    if (i < N) g_scan[i] = sh[threadIdx.x];
    if (threadIdx.x == SCAN_BLK - 1) g_bsum[blockIdx.x] = sh[threadIdx.x];
}

__global__ void scan2_kernel(int nb) {
    __shared__ int sh[SCAN_BLK];
    int t = threadIdx.x;
    int v = (t < nb) ? g_bsum[t] : 0;
    sh[t] = v;
    __syncthreads();
    for (int off = 1; off < SCAN_BLK; off <<= 1) {
        int u = (t >= off) ? sh[t - off] : 0;
        __syncthreads();
        sh[t] += u;
        __syncthreads();
    }
    g_bsum[t] = sh[t] - v;  // exclusive
}

__global__ void scan3_kernel(int N) {
    int i = blockIdx.x * blockDim.x + threadIdx.x;
    if (i >= N) return;
    int incl = g_scan[i] + g_bsum[i >> 8];
    g_rowptr[i + 1] = incl;
    g_cursor[i] = incl - g_deg[i];
    if (i == 0) g_rowptr[0] = 0;
}

__global__ void scatter_kernel(int ET) {
    int i = blockIdx.x * blockDim.x + threadIdx.x;
    if (i >= ET) return;
    int d = g_dst[i];
    int pos = atomicAdd(&g_cursor[d], 1);
    g_csrc[pos] = g_src[i];
}

// ---------------- GEMM: Y[N,128] = X[N,128] @ W[128,128] + b ----------------
// 128 threads (one output column each), 16 nodes per block, float4 LDS.
__global__ void gemm128_kernel(const float* __restrict__ X,
                               const float* __restrict__ W,
                               const float* __restrict__ b,
                               float* __restrict__ Y, int N) {
    __shared__ float4 sh[16 * 32];
    int n0 = blockIdx.x * 16;
    int tid = threadIdx.x;
    const float4* Xv = (const float4*)X;
    for (int i = tid; i < 16 * 32; i += 128) {
        int r = i >> 5, c = i & 31;
        int n = n0 + r;
        sh[i] = (n < N) ? Xv[(size_t)n * 32 + c] : make_float4(0.f, 0.f, 0.f, 0.f);
    }
    __syncthreads();
    float acc[16];
#pragma unroll
    for (int r = 0; r < 16; r++) acc[r] = 0.f;
#pragma unroll 2
    for (int kk = 0; kk < 32; kk++) {
        float w0 = W[(4 * kk + 0) * 128 + tid];
        float w1 = W[(4 * kk + 1) * 128 + tid];
        float w2 = W[(4 * kk + 2) * 128 + tid];
        float w3 = W[(4 * kk + 3) * 128 + tid];
#pragma unroll
        for (int r = 0; r < 16; r++) {
            float4 xv = sh[r * 32 + kk];
            acc[r] += xv.x * w0 + xv.y * w1 + xv.z * w2 + xv.w * w3;
        }
    }
    float bb = b[tid];
#pragma unroll
    for (int r = 0; r < 16; r++) {
        int n = n0 + r;
        if (n < N) Y[(size_t)n * 128 + tid] = acc[r] + bb;
    }
}

// GEMM: Y[N,32] = X[N,128] @ W[128,32] + b. 4 warps/block, 16 rows per warp.
__global__ void gemm32_kernel(const float* __restrict__ X,
                              const float* __restrict__ W,
                              const float* __restrict__ b,
                              float* __restrict__ Y, int N) {
    __shared__ float4 sh[64 * 32];
    int n0 = blockIdx.x * 64;
    int tid = threadIdx.x;
    int warp = tid >> 5, lane = tid & 31;
    const float4* Xv = (const float4*)X;
    for (int i = tid; i < 64 * 32; i += 128) {
        int r = i >> 5, c = i & 31;
        int n = n0 + r;
        sh[i] = (n < N) ? Xv[(size_t)n * 32 + c] : make_float4(0.f, 0.f, 0.f, 0.f);
    }
    __syncthreads();
    float acc[16];
#pragma unroll
    for (int r = 0; r < 16; r++) acc[r] = 0.f;
#pragma unroll 2
    for (int kk = 0; kk < 32; kk++) {
        float w0 = W[(4 * kk + 0) * 32 + lane];
        float w1 = W[(4 * kk + 1) * 32 + lane];
        float w2 = W[(4 * kk + 2) * 32 + lane];
        float w3 = W[(4 * kk + 3) * 32 + lane];
#pragma unroll
        for (int r = 0; r < 16; r++) {
            float4 xv = sh[(warp * 16 + r) * 32 + kk];
            acc[r] += xv.x * w0 + xv.y * w1 + xv.z * w2 + xv.w * w3;
        }
    }
    float bb = b[lane];
#pragma unroll
    for (int r = 0; r < 16; r++) {
        int n = n0 + warp * 16 + r;
        if (n < N) Y[(size_t)n * 32 + lane] = acc[r] + bb;
    }
}

// ---------------- fused GATv2 per-node kernel -------------------------------
// Warp per dst node. Lane owns channel `lane` of every head. Online softmax:
// running max m, denom d, accumulator acc all in registers -> zero atomics,
// single pass over the node's CSR edge list, fused bias+ELU (+pool) epilogue.
template <int H, bool POOL>
__global__ void gat_node_kernel(const float* __restrict__ att,
                                const float* __restrict__ bias, int N) {
    int n = (blockIdx.x * blockDim.x + threadIdx.x) >> 5;
    int lane = threadIdx.x & 31;
    if (n >= N) return;

    float attv[H], xrv[H], m[H], d[H], acc[H];
    const float* xr = g_xr + (size_t)n * (H * 32);
#pragma unroll
    for (int h = 0; h < H; h++) {
        attv[h] = __ldg(att + h * 32 + lane);
        xrv[h] = xr[h * 32 + lane];
        m[h] = -INFINITY; d[h] = 0.f; acc[h] = 0.f;
    }

    int e = g_rowptr[n], end = g_rowptr[n + 1];
    int s_next = (e < end) ? g_csrc[e] : 0;
    for (; e < end; e++) {
        int s = s_next;
        if (e + 1 < end) s_next = g_csrc[e + 1];
        const float* pl = g_xl + (size_t)s * (H * 32);
        float xlv[H], part[H];
#pragma unroll
        for (int h = 0; h < H; h++) {
            xlv[h] = pl[h * 32 + lane];
            float t = xlv[h] + xrv[h];
            t = t > 0.f ? t : 0.2f * t;
            part[h] = t * attv[h];
        }
#pragma unroll
        for (int h = 0; h < H; h++)
#pragma unroll
            for (int off = 16; off; off >>= 1)
                part[h] += __shfl_xor_sync(0xffffffffu, part[h], off);
#pragma unroll
        for (int h = 0; h < H; h++) {
            float lg = part[h];
            if (lg > m[h]) {  // warp-uniform branch
                float sc = __expf(m[h] - lg);  // exp(-inf)=0 on first edge
                d[h] *= sc; acc[h] *= sc; m[h] = lg;
            }
            float w = __expf(lg - m[h]);
            d[h] += w;
            acc[h] += w * xlv[h];
        }
    }

#pragma unroll
    for (int h = 0; h < H; h++) {
        float v = acc[h] / (d[h] + 1e-16f) + __ldg(bias + h * 32 + lane);
        v = v > 0.f ? v : expm1f(v);  // ELU
        if (POOL) {
            int b = g_batch[n];
            atomicAdd(&g_pool[b * 32 + lane], v);
            if (lane == 0) atomicAdd(&g_cnt[b], 1.f);
        } else {
            g_h[(size_t)n * (H * 32) + h * 32 + lane] = v;
        }
    }
}

// ---------------- pooling init + MLP head -----------------------------------
__global__ void pool_init_kernel(int B) {
    int i = blockIdx.x * blockDim.x + threadIdx.x;
    if (i < B * 32) g_pool[i] = 0.f;
    if (i < B) g_cnt[i] = 0.f;
}

__global__ void head_kernel(const float* __restrict__ meta,
                            const float* __restrict__ Wh1,
                            const float* __restrict__ bh1,
                            const float* __restrict__ Wh2,
                            const float* __restrict__ bh2,
                            float* __restrict__ out, int B) {
    int g = (blockIdx.x * blockDim.x + threadIdx.x) >> 5;
    int lane = threadIdx.x & 31;
    if (g >= B) return;
    float c = g_cnt[g];
    if (c < 1.f) c = 1.f;
    float inv = 1.f / c;
    float acc = bh1[lane];
    for (int k = 0; k < 32; k++)
        acc += g_pool[g * 32 + k] * inv * Wh1[k * 32 + lane];
    for (int k = 0; k < 12; k++)
        acc += meta[g * 12 + k] * Wh1[(32 + k) * 32 + lane];
    acc = acc > 0.f ? acc : 0.f;
    float r = acc * Wh2[lane];
#pragma unroll
    for (int off = 16; off; off >>= 1)
        r += __shfl_xor_sync(0xffffffffu, r, off);
    if (lane == 0) out[g] = r + bh2[0];
}

// ---------------- host ------------------------------------------------------
extern "C" void kernel_launch(void* const* d_in, const int* in_sizes, int n_in,
                              void* d_out, int out_size) {
    const float* x     = (const float*)d_in[0];
    const void*  ei    = d_in[1];
    const void*  batch = d_in[2];
    const float* meta  = (const float*)d_in[3];

    const float *Wl[3], *bl[3], *Wr[3], *br[3], *att[3], *bo[3];
    for (int l = 0; l < 3; l++) {
        int base = 4 + 6 * l;
        Wl[l]  = (const float*)d_in[base + 0];
        bl[l]  = (const float*)d_in[base + 1];
        Wr[l]  = (const float*)d_in[base + 2];
        br[l]  = (const float*)d_in[base + 3];
        att[l] = (const float*)d_in[base + 4];
        bo[l]  = (const float*)d_in[base + 5];
    }
    const float* Wh1 = (const float*)d_in[22];
    const float* bh1 = (const float*)d_in[23];
    const float* Wh2 = (const float*)d_in[24];
    const float* bh2 = (const float*)d_in[25];

    int N = in_sizes[0] / 128;
    int E = in_sizes[1] / 2;
    int ET = E + N;
    int B = in_sizes[3] / 12;
    float* out = (float*)d_out;

    float *p_xl, *p_xr, *p_h;
    cudaGetSymbolAddress((void**)&p_xl, g_xl);
    cudaGetSymbolAddress((void**)&p_xr, g_xr);
    cudaGetSymbolAddress((void**)&p_h, g_h);

    // ---- edge preprocessing + CSR build (once; graph shared by all layers)
    detect_kernel<<<1, 256>>>(ei);
    convert_kernel<<<(ET + 255) / 256, 256>>>(ei, batch, E, N);
    hist_kernel<<<(ET + 255) / 256, 256>>>(ET);
    int nb = (N + SCAN_BLK - 1) / SCAN_BLK;
    scan1_kernel<<<nb, SCAN_BLK>>>(N);
    scan2_kernel<<<1, SCAN_BLK>>>(nb);
    scan3_kernel<<<(N + 255) / 256, 256>>>(N);
    scatter_kernel<<<(ET + 255) / 256, 256>>>(ET);

    int g16 = (N + 15) / 16;
    int g64 = (N + 63) / 64;
    int node_blocks = (N * 32 + 255) / 256;

    pool_init_kernel<<<(B * 32 + 255) / 256, 256>>>(B);

    // ---- layers 0 and 1: H=4, DOUT=128
    for (int l = 0; l < 2; l++) {
        const float* X = (l == 0) ? x : p_h;
        gemm128_kernel<<<g16, 128>>>(X, Wl[l], bl[l], p_xl, N);
        gemm128_kernel<<<g16, 128>>>(X, Wr[l], br[l], p_xr, N);
        gat_node_kernel<4, false><<<node_blocks, 256>>>(att[l], bo[l], N);
    }

    // ---- layer 2: H=1, DOUT=32, pool fused into epilogue
    gemm32_kernel<<<g64, 128>>>(p_h, Wl[2], bl[2], p_xl, N);
    gemm32_kernel<<<g64, 128>>>(p_h, Wr[2], br[2], p_xr, N);
    gat_node_kernel<1, true><<<node_blocks, 256>>>(att[2], bo[2], N);

    // ---- MLP head
    head_kernel<<<(B * 32 + 255) / 256, 256>>>(meta, Wh1, bh1, Wh2, bh2, out, B);
}

// round 7
// speedup vs baseline: 2.0581x; 1.1400x over previous
#include <cuda_runtime.h>
#include <math.h>

#define NMAX 50000
#define EMAX 800000
#define ETMAX (NMAX + EMAX)
#define BMAX 512
#define SCAN_BLK 256

// ---------------- scratch (device globals; no allocations allowed) ----------
__device__ float g_xl[NMAX * 128];
__device__ float g_xr[NMAX * 128];
__device__ float g_h[NMAX * 128];
__device__ int   g_src[ETMAX];
__device__ int   g_dst[ETMAX];
__device__ int   g_csrc[ETMAX];      // src node per dst-sorted edge
__device__ int   g_deg[NMAX];
__device__ int   g_scan[NMAX];
__device__ int   g_bsum[SCAN_BLK];
__device__ int   g_rowptr[NMAX + 1];
__device__ int   g_cursor[NMAX];
__device__ int   g_batch[NMAX];
__device__ float g_pool[BMAX * 32];
__device__ float g_cnt[BMAX];
__device__ int   g_is64;

// ---------------- f32x2 packed math helpers ---------------------------------
__device__ __forceinline__ unsigned long long pack2(float lo, float hi) {
    unsigned long long r;
    asm("mov.b64 %0, {%1, %2};" : "=l"(r) : "f"(lo), "f"(hi));
    return r;
}
__device__ __forceinline__ void fma2(unsigned long long& acc,
                                     unsigned long long a,
                                     unsigned long long b) {
    asm("fma.rn.f32x2 %0, %1, %2, %0;" : "+l"(acc) : "l"(a), "l"(b));
}
__device__ __forceinline__ float hsum2(unsigned long long v) {
    float lo, hi;
    asm("mov.b64 {%0, %1}, %2;" : "=f"(lo), "=f"(hi) : "l"(v));
    return lo + hi;
}

// ---------------- dtype sniff: int64 vs int32 edge_index --------------------
__global__ void detect_kernel(const void* ei) {
    __shared__ int s;
    if (threadIdx.x == 0) s = 0;
    __syncthreads();
    const int* w = (const int*)ei;
    int v = w[2 * threadIdx.x + 1];
    atomicOr(&s, v);
    __syncthreads();
    if (threadIdx.x == 0) g_is64 = (s == 0) ? 1 : 0;
}

// Convert edge_index (+ self loops) and batch to int32; zero degree counters.
__global__ void convert_kernel(const void* ei, const void* batch, int E, int N) {
    int i = blockIdx.x * blockDim.x + threadIdx.x;
    int is64 = g_is64;
    if (i < E) {
        int s, d;
        if (is64) {
            const long long* p = (const long long*)ei;
            s = (int)p[i]; d = (int)p[(long long)E + i];
        } else {
            const int* p = (const int*)ei;
            s = p[i]; d = p[E + i];
        }
        g_src[i] = s; g_dst[i] = d;
    } else if (i < E + N) {
        int n = i - E;
        g_src[i] = n; g_dst[i] = n;
    }
    if (i < N) {
        g_batch[i] = is64 ? (int)((const long long*)batch)[i]
                          : ((const int*)batch)[i];
        g_deg[i] = 0;
    }
}

// ---------------- CSR build: histogram -> scan -> scatter -------------------
__global__ void hist_kernel(int ET) {
    int i = blockIdx.x * blockDim.x + threadIdx.x;
    if (i < ET) atomicAdd(&g_deg[g_dst[i]], 1);
}

__global__ void scan1_kernel(int N) {
    __shared__ int sh[SCAN_BLK];
    int i = blockIdx.x * SCAN_BLK + threadIdx.x;
    int v = (i < N) ? g_deg[i] : 0;
    sh[threadIdx.x] = v;
    __syncthreads();
    for (int off = 1; off < SCAN_BLK; off <<= 1) {
        int t = (threadIdx.x >= off) ? sh[threadIdx.x - off] : 0;
        __syncthreads();
        sh[threadIdx.x] += t;
        __syncthreads();
    }
    if (i < N) g_scan[i] = sh[threadIdx.x];
    if (threadIdx.x == SCAN_BLK - 1) g_bsum[blockIdx.x] = sh[threadIdx.x];
}

__global__ void scan2_kernel(int nb) {
    __shared__ int sh[SCAN_BLK];
    int t = threadIdx.x;
    int v = (t < nb) ? g_bsum[t] : 0;
    sh[t] = v;
    __syncthreads();
    for (int off = 1; off < SCAN_BLK; off <<= 1) {
        int u = (t >= off) ? sh[t - off] : 0;
        __syncthreads();
        sh[t] += u;
        __syncthreads();
    }
    g_bsum[t] = sh[t] - v;  // exclusive
}

__global__ void scan3_kernel(int N) {
    int i = blockIdx.x * blockDim.x + threadIdx.x;
    if (i >= N) return;
    int incl = g_scan[i] + g_bsum[i >> 8];
    g_rowptr[i + 1] = incl;
    g_cursor[i] = incl - g_deg[i];
    if (i == 0) g_rowptr[0] = 0;
}

__global__ void scatter_kernel(int ET) {
    int i = blockIdx.x * blockDim.x + threadIdx.x;
    if (i >= ET) return;
    int d = g_dst[i];
    int pos = atomicAdd(&g_cursor[d], 1);
    g_csrc[pos] = g_src[i];
}

// ---------------- GEMM: Y[N,128] = X[N,128] @ W[128,128] + b ----------------
// 128 threads (one output column each), 16 nodes per block. Inner product in
// packed f32x2 (FFMA2): pairs along k -> half the fma-pipe instructions.
__global__ void gemm128_kernel(const float* __restrict__ X,
                               const float* __restrict__ W,
                               const float* __restrict__ b,
                               float* __restrict__ Y, int N) {
    __shared__ float4 sh[16 * 32];
    int n0 = blockIdx.x * 16;
    int tid = threadIdx.x;
    const float4* Xv = (const float4*)X;
    for (int i = tid; i < 16 * 32; i += 128) {
        int r = i >> 5, c = i & 31;
        int n = n0 + r;
        sh[i] = (n < N) ? Xv[(size_t)n * 32 + c] : make_float4(0.f, 0.f, 0.f, 0.f);
    }
    __syncthreads();
    unsigned long long acc[16];
#pragma unroll
    for (int r = 0; r < 16; r++) acc[r] = 0ull;
    const ulonglong2* shv = (const ulonglong2*)sh;
#pragma unroll 2
    for (int kk = 0; kk < 32; kk++) {
        float w0 = W[(4 * kk + 0) * 128 + tid];
        float w1 = W[(4 * kk + 1) * 128 + tid];
        float w2 = W[(4 * kk + 2) * 128 + tid];
        float w3 = W[(4 * kk + 3) * 128 + tid];
        unsigned long long ww01 = pack2(w0, w1);
        unsigned long long ww23 = pack2(w2, w3);
#pragma unroll
        for (int r = 0; r < 16; r++) {
            ulonglong2 xv = shv[r * 32 + kk];
            fma2(acc[r], xv.x, ww01);
            fma2(acc[r], xv.y, ww23);
        }
    }
    float bb = b[tid];
#pragma unroll
    for (int r = 0; r < 16; r++) {
        int n = n0 + r;
        if (n < N) Y[(size_t)n * 128 + tid] = hsum2(acc[r]) + bb;
    }
}

// GEMM: Y[N,32] = X[N,128] @ W[128,32] + b. 4 warps/block, 16 rows per warp.
__global__ void gemm32_kernel(const float* __restrict__ X,
                              const float* __restrict__ W,
                              const float* __restrict__ b,
                              float* __restrict__ Y, int N) {
    __shared__ float4 sh[64 * 32];
    int n0 = blockIdx.x * 64;
    int tid = threadIdx.x;
    int warp = tid >> 5, lane = tid & 31;
    const float4* Xv = (const float4*)X;
    for (int i = tid; i < 64 * 32; i += 128) {
        int r = i >> 5, c = i & 31;
        int n = n0 + r;
        sh[i] = (n < N) ? Xv[(size_t)n * 32 + c] : make_float4(0.f, 0.f, 0.f, 0.f);
    }
    __syncthreads();
    unsigned long long acc[16];
#pragma unroll
    for (int r = 0; r < 16; r++) acc[r] = 0ull;
    const ulonglong2* shv = (const ulonglong2*)sh;
#pragma unroll 2
    for (int kk = 0; kk < 32; kk++) {
        float w0 = W[(4 * kk + 0) * 32 + lane];
        float w1 = W[(4 * kk + 1) * 32 + lane];
        float w2 = W[(4 * kk + 2) * 32 + lane];
        float w3 = W[(4 * kk + 3) * 32 + lane];
        unsigned long long ww01 = pack2(w0, w1);
        unsigned long long ww23 = pack2(w2, w3);
#pragma unroll
        for (int r = 0; r < 16; r++) {
            ulonglong2 xv = shv[(warp * 16 + r) * 32 + kk];
            fma2(acc[r], xv.x, ww01);
            fma2(acc[r], xv.y, ww23);
        }
    }
    float bb = b[lane];
#pragma unroll
    for (int r = 0; r < 16; r++) {
        int n = n0 + warp * 16 + r;
        if (n < N) Y[(size_t)n * 32 + lane] = hsum2(acc[r]) + bb;
    }
}

// ---------------- multi-head warp reduce ------------------------------------
// Reduces 4 per-lane values to 4 warp sums in 6 shfl (vs 20 for 4 butterflies).
// Result: lane group [8h, 8h+8) holds the full sum of head h.
__device__ __forceinline__ float reduce4(const float part[4], int lane) {
    bool hi16 = (lane & 16) != 0;
    bool hi8  = (lane & 8) != 0;
    float u  = hi16 ? part[2] : part[0];
    float uv = hi16 ? part[0] : part[2];
    u += __shfl_xor_sync(0xffffffffu, uv, 16);
    float w  = hi16 ? part[3] : part[1];
    float wv = hi16 ? part[1] : part[3];
    w += __shfl_xor_sync(0xffffffffu, wv, 16);
    float p = hi8 ? w : u;
    float q = hi8 ? u : w;
    p += __shfl_xor_sync(0xffffffffu, q, 8);
    p += __shfl_xor_sync(0xffffffffu, p, 4);
    p += __shfl_xor_sync(0xffffffffu, p, 2);
    p += __shfl_xor_sync(0xffffffffu, p, 1);
    return p;
}

// ---------------- fused GATv2 per-node kernel, H=4 --------------------------
// Warp per dst node, online softmax in registers, 2 edges per iteration for
// load/shfl pipelining. Zero atomics.
__global__ void gat_node4_kernel(const float* __restrict__ att,
                                 const float* __restrict__ bias, int N) {
    int n = (blockIdx.x * blockDim.x + threadIdx.x) >> 5;
    int lane = threadIdx.x & 31;
    if (n >= N) return;

    float attv[4], xrv[4], m[4], d[4], acc[4];
    const float* xr = g_xr + (size_t)n * 128;
#pragma unroll
    for (int h = 0; h < 4; h++) {
        attv[h] = __ldg(att + h * 32 + lane);
        xrv[h] = xr[h * 32 + lane];
        m[h] = -INFINITY; d[h] = 0.f; acc[h] = 0.f;
    }

    int e = g_rowptr[n], end = g_rowptr[n + 1];
    for (; e + 1 < end; e += 2) {
        int s0 = g_csrc[e], s1 = g_csrc[e + 1];
        const float* p0 = g_xl + (size_t)s0 * 128;
        const float* p1 = g_xl + (size_t)s1 * 128;
        float xl0[4], xl1[4], pa[4], pb[4];
#pragma unroll
        for (int h = 0; h < 4; h++) {
            xl0[h] = p0[h * 32 + lane];
            xl1[h] = p1[h * 32 + lane];
        }
#pragma unroll
        for (int h = 0; h < 4; h++) {
            float t0 = xl0[h] + xrv[h];
            t0 = t0 > 0.f ? t0 : 0.2f * t0;
            pa[h] = t0 * attv[h];
            float t1 = xl1[h] + xrv[h];
            t1 = t1 > 0.f ? t1 : 0.2f * t1;
            pb[h] = t1 * attv[h];
        }
        float ra = reduce4(pa, lane);
        float rb = reduce4(pb, lane);
#pragma unroll
        for (int h = 0; h < 4; h++) {
            float lg = __shfl_sync(0xffffffffu, ra, h << 3);
            if (lg > m[h]) {
                float sc = __expf(m[h] - lg);
                d[h] *= sc; acc[h] *= sc; m[h] = lg;
            }
            float wg = __expf(lg - m[h]);
            d[h] += wg;
            acc[h] += wg * xl0[h];
        }
#pragma unroll
        for (int h = 0; h < 4; h++) {
            float lg = __shfl_sync(0xffffffffu, rb, h << 3);
            if (lg > m[h]) {
                float sc = __expf(m[h] - lg);
                d[h] *= sc; acc[h] *= sc; m[h] = lg;
            }
            float wg = __expf(lg - m[h]);
            d[h] += wg;
            acc[h] += wg * xl1[h];
        }
    }
    if (e < end) {
        int s0 = g_csrc[e];
        const float* p0 = g_xl + (size_t)s0 * 128;
        float xl0[4], pa[4];
#pragma unroll
        for (int h = 0; h < 4; h++) {
            xl0[h] = p0[h * 32 + lane];
            float t0 = xl0[h] + xrv[h];
            t0 = t0 > 0.f ? t0 : 0.2f * t0;
            pa[h] = t0 * attv[h];
        }
        float ra = reduce4(pa, lane);
#pragma unroll
        for (int h = 0; h < 4; h++) {
            float lg = __shfl_sync(0xffffffffu, ra, h << 3);
            if (lg > m[h]) {
                float sc = __expf(m[h] - lg);
                d[h] *= sc; acc[h] *= sc; m[h] = lg;
            }
            float wg = __expf(lg - m[h]);
            d[h] += wg;
            acc[h] += wg * xl0[h];
        }
    }

#pragma unroll
    for (int h = 0; h < 4; h++) {
        float v = acc[h] / (d[h] + 1e-16f) + __ldg(bias + h * 32 + lane);
        v = v > 0.f ? v : (__expf(v) - 1.f);  // ELU (v<0 path)
        g_h[(size_t)n * 128 + h * 32 + lane] = v;
    }
}

// ---------------- fused GATv2 per-node kernel, H=1 + pooling ----------------
__global__ void gat_node1_kernel(const float* __restrict__ att,
                                 const float* __restrict__ bias, int N) {
    int n = (blockIdx.x * blockDim.x + threadIdx.x) >> 5;
    int lane = threadIdx.x & 31;
    if (n >= N) return;

    float attv = __ldg(att + lane);
    float xrv = g_xr[(size_t)n * 32 + lane];
    float m = -INFINITY, d = 0.f, acc = 0.f;

    int e = g_rowptr[n], end = g_rowptr[n + 1];
    for (; e + 1 < end; e += 2) {
        int s0 = g_csrc[e], s1 = g_csrc[e + 1];
        float xl0 = g_xl[(size_t)s0 * 32 + lane];
        float xl1 = g_xl[(size_t)s1 * 32 + lane];
        float t0 = xl0 + xrv; t0 = t0 > 0.f ? t0 : 0.2f * t0;
        float t1 = xl1 + xrv; t1 = t1 > 0.f ? t1 : 0.2f * t1;
        float pa = t0 * attv, pb = t1 * attv;
#pragma unroll
        for (int off = 16; off; off >>= 1) {
            pa += __shfl_xor_sync(0xffffffffu, pa, off);
            pb += __shfl_xor_sync(0xffffffffu, pb, off);
        }
        if (pa > m) {
            float sc = __expf(m - pa);
            d *= sc; acc *= sc; m = pa;
        }
        float wg = __expf(pa - m);
        d += wg; acc += wg * xl0;
        if (pb > m) {
            float sc = __expf(m - pb);
            d *= sc; acc *= sc; m = pb;
        }
        wg = __expf(pb - m);
        d += wg; acc += wg * xl1;
    }
    if (e < end) {
        int s0 = g_csrc[e];
        float xl0 = g_xl[(size_t)s0 * 32 + lane];
        float t0 = xl0 + xrv; t0 = t0 > 0.f ? t0 : 0.2f * t0;
        float pa = t0 * attv;
#pragma unroll
        for (int off = 16; off; off >>= 1)
            pa += __shfl_xor_sync(0xffffffffu, pa, off);
        if (pa > m) {
            float sc = __expf(m - pa);
            d *= sc; acc *= sc; m = pa;
        }
        float wg = __expf(pa - m);
        d += wg; acc += wg * xl0;
    }

    float v = acc / (d + 1e-16f) + __ldg(bias + lane);
    v = v > 0.f ? v : (__expf(v) - 1.f);
    int b = g_batch[n];
    atomicAdd(&g_pool[b * 32 + lane], v);
    if (lane == 0) atomicAdd(&g_cnt[b], 1.f);
}

// ---------------- pooling init + MLP head -----------------------------------
__global__ void pool_init_kernel(int B) {
    int i = blockIdx.x * blockDim.x + threadIdx.x;
    if (i < B * 32) g_pool[i] = 0.f;
    if (i < B) g_cnt[i] = 0.f;
}

__global__ void head_kernel(const float* __restrict__ meta,
                            const float* __restrict__ Wh1,
                            const float* __restrict__ bh1,
                            const float* __restrict__ Wh2,
                            const float* __restrict__ bh2,
                            float* __restrict__ out, int B) {
    int g = (blockIdx.x * blockDim.x + threadIdx.x) >> 5;
    int lane = threadIdx.x & 31;
    if (g >= B) return;
    float c = g_cnt[g];
    if (c < 1.f) c = 1.f;
    float inv = 1.f / c;
    float acc = bh1[lane];
    for (int k = 0; k < 32; k++)
        acc += g_pool[g * 32 + k] * inv * Wh1[k * 32 + lane];
    for (int k = 0; k < 12; k++)
        acc += meta[g * 12 + k] * Wh1[(32 + k) * 32 + lane];
    acc = acc > 0.f ? acc : 0.f;
    float r = acc * Wh2[lane];
#pragma unroll
    for (int off = 16; off; off >>= 1)
        r += __shfl_xor_sync(0xffffffffu, r, off);
    if (lane == 0) out[g] = r + bh2[0];
}

// ---------------- host ------------------------------------------------------
extern "C" void kernel_launch(void* const* d_in, const int* in_sizes, int n_in,
                              void* d_out, int out_size) {
    const float* x     = (const float*)d_in[0];
    const void*  ei    = d_in[1];
    const void*  batch = d_in[2];
    const float* meta  = (const float*)d_in[3];

    const float *Wl[3], *bl[3], *Wr[3], *br[3], *att[3], *bo[3];
    for (int l = 0; l < 3; l++) {
        int base = 4 + 6 * l;
        Wl[l]  = (const float*)d_in[base + 0];
        bl[l]  = (const float*)d_in[base + 1];
        Wr[l]  = (const float*)d_in[base + 2];
        br[l]  = (const float*)d_in[base + 3];
        att[l] = (const float*)d_in[base + 4];
        bo[l]  = (const float*)d_in[base + 5];
    }
    const float* Wh1 = (const float*)d_in[22];
    const float* bh1 = (const float*)d_in[23];
    const float* Wh2 = (const float*)d_in[24];
    const float* bh2 = (const float*)d_in[25];

    int N = in_sizes[0] / 128;
    int E = in_sizes[1] / 2;
    int ET = E + N;
    int B = in_sizes[3] / 12;
    float* out = (float*)d_out;

    float *p_xl, *p_xr, *p_h;
    cudaGetSymbolAddress((void**)&p_xl, g_xl);
    cudaGetSymbolAddress((void**)&p_xr, g_xr);
    cudaGetSymbolAddress((void**)&p_h, g_h);

    // ---- edge preprocessing + CSR build (once; graph shared by all layers)
    detect_kernel<<<1, 256>>>(ei);
    convert_kernel<<<(ET + 255) / 256, 256>>>(ei, batch, E, N);
    hist_kernel<<<(ET + 255) / 256, 256>>>(ET);
    int nb = (N + SCAN_BLK - 1) / SCAN_BLK;
    scan1_kernel<<<nb, SCAN_BLK>>>(N);
    scan2_kernel<<<1, SCAN_BLK>>>(nb);
    scan3_kernel<<<(N + 255) / 256, 256>>>(N);
    scatter_kernel<<<(ET + 255) / 256, 256>>>(ET);

    int g16 = (N + 15) / 16;
    int g64 = (N + 63) / 64;
    int node_blocks = (N * 32 + 255) / 256;

    pool_init_kernel<<<(B * 32 + 255) / 256, 256>>>(B);

    // ---- layers 0 and 1: H=4, DOUT=128
    for (int l = 0; l < 2; l++) {
        const float* X = (l == 0) ? x : p_h;
        gemm128_kernel<<<g16, 128>>>(X, Wl[l], bl[l], p_xl, N);
        gemm128_kernel<<<g16, 128>>>(X, Wr[l], br[l], p_xr, N);
        gat_node4_kernel<<<node_blocks, 256>>>(att[l], bo[l], N);
    }

    // ---- layer 2: H=1, DOUT=32, pool fused into epilogue
    gemm32_kernel<<<g64, 128>>>(p_h, Wl[2], bl[2], p_xl, N);
    gemm32_kernel<<<g64, 128>>>(p_h, Wr[2], br[2], p_xr, N);
    gat_node1_kernel<<<node_blocks, 256>>>(att[2], bo[2], N);

    // ---- MLP head
    head_kernel<<<(B * 32 + 255) / 256, 256>>>(meta, Wh1, bh1, Wh2, bh2, out, B);
}

// round 8
// speedup vs baseline: 2.1457x; 1.0426x over previous
#include <cuda_runtime.h>
#include <math.h>

#define NMAX 50000
#define EMAX 800000
#define ETMAX (NMAX + EMAX)
#define BMAX 512
#define SCAN_BLK 256

// ---------------- scratch (device globals; no allocations allowed) ----------
__device__ float g_xl[NMAX * 128];
__device__ float g_xr[NMAX * 128];
__device__ float g_h[NMAX * 128];
__device__ int   g_src[ETMAX];
__device__ int   g_dst[ETMAX];
__device__ int   g_csrc[ETMAX];      // src node per dst-sorted edge
__device__ int   g_deg[NMAX];
__device__ int   g_scan[NMAX];
__device__ int   g_bsum[SCAN_BLK];
__device__ int   g_rowptr[NMAX + 1];
__device__ int   g_cursor[NMAX];
__device__ int   g_batch[NMAX];
__device__ float g_pool[BMAX * 32];
__device__ float g_cnt[BMAX];
__device__ int   g_is64;
// packed weights: wp[kk][col] = ulonglong2{(W[4kk],W[4kk+1]),(W[4kk+2],W[4kk+3])}
__device__ ulonglong2 g_wpl[32 * 128];
__device__ ulonglong2 g_wpr[32 * 128];

// ---------------- f32x2 packed math helpers ---------------------------------
__device__ __forceinline__ unsigned long long pack2(float lo, float hi) {
    unsigned long long r;
    asm("mov.b64 %0, {%1, %2};" : "=l"(r) : "f"(lo), "f"(hi));
    return r;
}
__device__ __forceinline__ void fma2(unsigned long long& acc,
                                     unsigned long long a,
                                     unsigned long long b) {
    asm("fma.rn.f32x2 %0, %1, %2, %0;" : "+l"(acc) : "l"(a), "l"(b));
}
__device__ __forceinline__ float hsum2(unsigned long long v) {
    float lo, hi;
    asm("mov.b64 {%0, %1}, %2;" : "=f"(lo), "=f"(hi) : "l"(v));
    return lo + hi;
}

// ---------------- dtype sniff: int64 vs int32 edge_index --------------------
__global__ void detect_kernel(const void* ei) {
    __shared__ int s;
    if (threadIdx.x == 0) s = 0;
    __syncthreads();
    const int* w = (const int*)ei;
    int v = w[2 * threadIdx.x + 1];
    atomicOr(&s, v);
    __syncthreads();
    if (threadIdx.x == 0) g_is64 = (s == 0) ? 1 : 0;
}

// Convert edge_index (+ self loops) and batch to int32; zero degree counters.
__global__ void convert_kernel(const void* ei, const void* batch, int E, int N) {
    int i = blockIdx.x * blockDim.x + threadIdx.x;
    int is64 = g_is64;
    if (i < E) {
        int s, d;
        if (is64) {
            const long long* p = (const long long*)ei;
            s = (int)p[i]; d = (int)p[(long long)E + i];
        } else {
            const int* p = (const int*)ei;
            s = p[i]; d = p[E + i];
        }
        g_src[i] = s; g_dst[i] = d;
    } else if (i < E + N) {
        int n = i - E;
        g_src[i] = n; g_dst[i] = n;
    }
    if (i < N) {
        g_batch[i] = is64 ? (int)((const long long*)batch)[i]
                          : ((const int*)batch)[i];
        g_deg[i] = 0;
    }
}

// ---------------- weight pre-pack -------------------------------------------
// Packs Wl and Wr [128, DOUT] into g_wpl/g_wpr f32x2-quad layout.
__global__ void pack_w_kernel(const float* __restrict__ Wl,
                              const float* __restrict__ Wr, int DOUT) {
    int i = blockIdx.x * blockDim.x + threadIdx.x;
    int tot = 32 * DOUT;
    if (i >= 2 * tot) return;
    const float* W = (i < tot) ? Wl : Wr;
    int j = (i < tot) ? i : i - tot;
    int kk = j / DOUT, col = j - kk * DOUT;
    ulonglong2 v;
    v.x = pack2(W[(4 * kk + 0) * DOUT + col], W[(4 * kk + 1) * DOUT + col]);
    v.y = pack2(W[(4 * kk + 2) * DOUT + col], W[(4 * kk + 3) * DOUT + col]);
    if (i < tot) g_wpl[j] = v; else g_wpr[j] = v;
}

// ---------------- CSR build: histogram -> scan -> scatter -------------------
__global__ void hist_kernel(int ET) {
    int i = blockIdx.x * blockDim.x + threadIdx.x;
    if (i < ET) atomicAdd(&g_deg[g_dst[i]], 1);
}

__global__ void scan1_kernel(int N) {
    __shared__ int sh[SCAN_BLK];
    int i = blockIdx.x * SCAN_BLK + threadIdx.x;
    int v = (i < N) ? g_deg[i] : 0;
    sh[threadIdx.x] = v;
    __syncthreads();
    for (int off = 1; off < SCAN_BLK; off <<= 1) {
        int t = (threadIdx.x >= off) ? sh[threadIdx.x - off] : 0;
        __syncthreads();
        sh[threadIdx.x] += t;
        __syncthreads();
    }
    if (i < N) g_scan[i] = sh[threadIdx.x];
    if (threadIdx.x == SCAN_BLK - 1) g_bsum[blockIdx.x] = sh[threadIdx.x];
}

__global__ void scan2_kernel(int nb) {
    __shared__ int sh[SCAN_BLK];
    int t = threadIdx.x;
    int v = (t < nb) ? g_bsum[t] : 0;
    sh[t] = v;
    __syncthreads();
    for (int off = 1; off < SCAN_BLK; off <<= 1) {
        int u = (t >= off) ? sh[t - off] : 0;
        __syncthreads();
        sh[t] += u;
        __syncthreads();
    }
    g_bsum[t] = sh[t] - v;  // exclusive
}

__global__ void scan3_kernel(int N) {
    int i = blockIdx.x * blockDim.x + threadIdx.x;
    if (i >= N) return;
    int incl = g_scan[i] + g_bsum[i >> 8];
    g_rowptr[i + 1] = incl;
    g_cursor[i] = incl - g_deg[i];
    if (i == 0) g_rowptr[0] = 0;
}

__global__ void scatter_kernel(int ET) {
    int i = blockIdx.x * blockDim.x + threadIdx.x;
    if (i >= ET) return;
    int d = g_dst[i];
    int pos = atomicAdd(&g_cursor[d], 1);
    g_csrc[pos] = g_src[i];
}

// ---------------- dual GEMM: Yl/Yr[N,128] = X[N,128] @ {Wl,Wr} + b ----------
// 128 threads (thread = output column for BOTH matrices), 8 rows per block.
// X tile staged once in shared; each LDS.128 feeds 4 FFMA2.
__global__ void gemm128_dual_kernel(const float* __restrict__ X,
                                    const float* __restrict__ bl,
                                    const float* __restrict__ br,
                                    float* __restrict__ Yl,
                                    float* __restrict__ Yr, int N) {
    __shared__ float4 sh[8 * 32];
    int n0 = blockIdx.x * 8;
    int tid = threadIdx.x;
    const float4* Xv = (const float4*)X;
    for (int i = tid; i < 8 * 32; i += 128) {
        int r = i >> 5, c = i & 31;
        int n = n0 + r;
        sh[i] = (n < N) ? Xv[(size_t)n * 32 + c] : make_float4(0.f, 0.f, 0.f, 0.f);
    }
    __syncthreads();
    unsigned long long accl[8], accr[8];
#pragma unroll
    for (int r = 0; r < 8; r++) { accl[r] = 0ull; accr[r] = 0ull; }
    const ulonglong2* shv = (const ulonglong2*)sh;
#pragma unroll 2
    for (int kk = 0; kk < 32; kk++) {
        ulonglong2 wl = g_wpl[kk * 128 + tid];
        ulonglong2 wr = g_wpr[kk * 128 + tid];
#pragma unroll
        for (int r = 0; r < 8; r++) {
            ulonglong2 xv = shv[r * 32 + kk];
            fma2(accl[r], xv.x, wl.x);
            fma2(accl[r], xv.y, wl.y);
            fma2(accr[r], xv.x, wr.x);
            fma2(accr[r], xv.y, wr.y);
        }
    }
    float bbl = bl[tid], bbr = br[tid];
#pragma unroll
    for (int r = 0; r < 8; r++) {
        int n = n0 + r;
        if (n < N) {
            Yl[(size_t)n * 128 + tid] = hsum2(accl[r]) + bbl;
            Yr[(size_t)n * 128 + tid] = hsum2(accr[r]) + bbr;
        }
    }
}

// dual GEMM DOUT=32: lane = column, 4 warps x 16 rows = 64 rows per block.
__global__ void gemm32_dual_kernel(const float* __restrict__ X,
                                   const float* __restrict__ bl,
                                   const float* __restrict__ br,
                                   float* __restrict__ Yl,
                                   float* __restrict__ Yr, int N) {
    __shared__ float4 sh[64 * 32];
    int n0 = blockIdx.x * 64;
    int tid = threadIdx.x;
    int warp = tid >> 5, lane = tid & 31;
    const float4* Xv = (const float4*)X;
    for (int i = tid; i < 64 * 32; i += 128) {
        int r = i >> 5, c = i & 31;
        int n = n0 + r;
        sh[i] = (n < N) ? Xv[(size_t)n * 32 + c] : make_float4(0.f, 0.f, 0.f, 0.f);
    }
    __syncthreads();
    unsigned long long accl[16], accr[16];
#pragma unroll
    for (int r = 0; r < 16; r++) { accl[r] = 0ull; accr[r] = 0ull; }
    const ulonglong2* shv = (const ulonglong2*)sh;
#pragma unroll 2
    for (int kk = 0; kk < 32; kk++) {
        ulonglong2 wl = g_wpl[kk * 32 + lane];
        ulonglong2 wr = g_wpr[kk * 32 + lane];
#pragma unroll
        for (int r = 0; r < 16; r++) {
            ulonglong2 xv = shv[(warp * 16 + r) * 32 + kk];
            fma2(accl[r], xv.x, wl.x);
            fma2(accl[r], xv.y, wl.y);
            fma2(accr[r], xv.x, wr.x);
            fma2(accr[r], xv.y, wr.y);
        }
    }
    float bbl = bl[lane], bbr = br[lane];
#pragma unroll
    for (int r = 0; r < 16; r++) {
        int n = n0 + warp * 16 + r;
        if (n < N) {
            Yl[(size_t)n * 32 + lane] = hsum2(accl[r]) + bbl;
            Yr[(size_t)n * 32 + lane] = hsum2(accr[r]) + bbr;
        }
    }
}

// ---------------- multi-head warp reduce ------------------------------------
// 4 per-lane values -> 4 warp sums in 6 shfl. Lane group [8h,8h+8) = head h.
__device__ __forceinline__ float reduce4(const float part[4], int lane) {
    bool hi16 = (lane & 16) != 0;
    bool hi8  = (lane & 8) != 0;
    float u  = hi16 ? part[2] : part[0];
    float uv = hi16 ? part[0] : part[2];
    u += __shfl_xor_sync(0xffffffffu, uv, 16);
    float w  = hi16 ? part[3] : part[1];
    float wv = hi16 ? part[1] : part[3];
    w += __shfl_xor_sync(0xffffffffu, wv, 16);
    float p = hi8 ? w : u;
    float q = hi8 ? u : w;
    p += __shfl_xor_sync(0xffffffffu, q, 8);
    p += __shfl_xor_sync(0xffffffffu, p, 4);
    p += __shfl_xor_sync(0xffffffffu, p, 2);
    p += __shfl_xor_sync(0xffffffffu, p, 1);
    return p;
}

// ---------------- fused GATv2 per-node kernel, H=4 --------------------------
// Warp per dst node, online softmax in registers, 4 edges per iteration
// (16 independent LDG in flight; 4 pipelined reduce chains). Zero atomics.
__global__ void gat_node4_kernel(const float* __restrict__ att,
                                 const float* __restrict__ bias, int N) {
    int n = (blockIdx.x * blockDim.x + threadIdx.x) >> 5;
    int lane = threadIdx.x & 31;
    if (n >= N) return;

    float attv[4], xrv[4], m[4], d[4], acc[4];
    const float* xr = g_xr + (size_t)n * 128;
#pragma unroll
    for (int h = 0; h < 4; h++) {
        attv[h] = __ldg(att + h * 32 + lane);
        xrv[h] = xr[h * 32 + lane];
        m[h] = -INFINITY; d[h] = 0.f; acc[h] = 0.f;
    }

    int e = g_rowptr[n], end = g_rowptr[n + 1];
    for (; e + 3 < end; e += 4) {
        int s0 = g_csrc[e], s1 = g_csrc[e + 1];
        int s2 = g_csrc[e + 2], s3 = g_csrc[e + 3];
        const float* p0 = g_xl + (size_t)s0 * 128;
        const float* p1 = g_xl + (size_t)s1 * 128;
        const float* p2 = g_xl + (size_t)s2 * 128;
        const float* p3 = g_xl + (size_t)s3 * 128;
        float xl[4][4], pt[4][4];
#pragma unroll
        for (int h = 0; h < 4; h++) {
            xl[0][h] = p0[h * 32 + lane];
            xl[1][h] = p1[h * 32 + lane];
            xl[2][h] = p2[h * 32 + lane];
            xl[3][h] = p3[h * 32 + lane];
        }
#pragma unroll
        for (int j = 0; j < 4; j++)
#pragma unroll
            for (int h = 0; h < 4; h++) {
                float t = xl[j][h] + xrv[h];
                t = t > 0.f ? t : 0.2f * t;
                pt[j][h] = t * attv[h];
            }
        float rr[4];
#pragma unroll
        for (int j = 0; j < 4; j++) rr[j] = reduce4(pt[j], lane);
#pragma unroll
        for (int j = 0; j < 4; j++)
#pragma unroll
            for (int h = 0; h < 4; h++) {
                float lg = __shfl_sync(0xffffffffu, rr[j], h << 3);
                if (lg > m[h]) {
                    float sc = __expf(m[h] - lg);
                    d[h] *= sc; acc[h] *= sc; m[h] = lg;
                }
                float wg = __expf(lg - m[h]);
                d[h] += wg;
                acc[h] += wg * xl[j][h];
            }
    }
    for (; e < end; e++) {
        int s0 = g_csrc[e];
        const float* p0 = g_xl + (size_t)s0 * 128;
        float xl0[4], pa[4];
#pragma unroll
        for (int h = 0; h < 4; h++) {
            xl0[h] = p0[h * 32 + lane];
            float t = xl0[h] + xrv[h];
            t = t > 0.f ? t : 0.2f * t;
            pa[h] = t * attv[h];
        }
        float ra = reduce4(pa, lane);
#pragma unroll
        for (int h = 0; h < 4; h++) {
            float lg = __shfl_sync(0xffffffffu, ra, h << 3);
            if (lg > m[h]) {
                float sc = __expf(m[h] - lg);
                d[h] *= sc; acc[h] *= sc; m[h] = lg;
            }
            float wg = __expf(lg - m[h]);
            d[h] += wg;
            acc[h] += wg * xl0[h];
        }
    }

#pragma unroll
    for (int h = 0; h < 4; h++) {
        float v = acc[h] / (d[h] + 1e-16f) + __ldg(bias + h * 32 + lane);
        v = v > 0.f ? v : (__expf(v) - 1.f);  // ELU (v<0 path)
        g_h[(size_t)n * 128 + h * 32 + lane] = v;
    }
}

// ---------------- fused GATv2 per-node kernel, H=1 + pooling ----------------
__global__ void gat_node1_kernel(const float* __restrict__ att,
                                 const float* __restrict__ bias, int N) {
    int n = (blockIdx.x * blockDim.x + threadIdx.x) >> 5;
    int lane = threadIdx.x & 31;
    if (n >= N) return;

    float attv = __ldg(att + lane);
    float xrv = g_xr[(size_t)n * 32 + lane];
    float m = -INFINITY, d = 0.f, acc = 0.f;

    int e = g_rowptr[n], end = g_rowptr[n + 1];
    for (; e + 1 < end; e += 2) {
        int s0 = g_csrc[e], s1 = g_csrc[e + 1];
        float xl0 = g_xl[(size_t)s0 * 32 + lane];
        float xl1 = g_xl[(size_t)s1 * 32 + lane];
        float t0 = xl0 + xrv; t0 = t0 > 0.f ? t0 : 0.2f * t0;
        float t1 = xl1 + xrv; t1 = t1 > 0.f ? t1 : 0.2f * t1;
        float pa = t0 * attv, pb = t1 * attv;
#pragma unroll
        for (int off = 16; off; off >>= 1) {
            pa += __shfl_xor_sync(0xffffffffu, pa, off);
            pb += __shfl_xor_sync(0xffffffffu, pb, off);
        }
        if (pa > m) {
            float sc = __expf(m - pa);
            d *= sc; acc *= sc; m = pa;
        }
        float wg = __expf(pa - m);
        d += wg; acc += wg * xl0;
        if (pb > m) {
            float sc = __expf(m - pb);
            d *= sc; acc *= sc; m = pb;
        }
        wg = __expf(pb - m);
        d += wg; acc += wg * xl1;
    }
    if (e < end) {
        int s0 = g_csrc[e];
        float xl0 = g_xl[(size_t)s0 * 32 + lane];
        float t0 = xl0 + xrv; t0 = t0 > 0.f ? t0 : 0.2f * t0;
        float pa = t0 * attv;
#pragma unroll
        for (int off = 16; off; off >>= 1)
            pa += __shfl_xor_sync(0xffffffffu, pa, off);
        if (pa > m) {
            float sc = __expf(m - pa);
            d *= sc; acc *= sc; m = pa;
        }
        float wg = __expf(pa - m);
        d += wg; acc += wg * xl0;
    }

    float v = acc / (d + 1e-16f) + __ldg(bias + lane);
    v = v > 0.f ? v : (__expf(v) - 1.f);
    int b = g_batch[n];
    atomicAdd(&g_pool[b * 32 + lane], v);
    if (lane == 0) atomicAdd(&g_cnt[b], 1.f);
}

// ---------------- pooling init + MLP head -----------------------------------
__global__ void pool_init_kernel(int B) {
    int i = blockIdx.x * blockDim.x + threadIdx.x;
    if (i < B * 32) g_pool[i] = 0.f;
    if (i < B) g_cnt[i] = 0.f;
}

__global__ void head_kernel(const float* __restrict__ meta,
                            const float* __restrict__ Wh1,
                            const float* __restrict__ bh1,
                            const float* __restrict__ Wh2,
                            const float* __restrict__ bh2,
                            float* __restrict__ out, int B) {
    int g = (blockIdx.x * blockDim.x + threadIdx.x) >> 5;
    int lane = threadIdx.x & 31;
    if (g >= B) return;
    float c = g_cnt[g];
    if (c < 1.f) c = 1.f;
    float inv = 1.f / c;
    float acc = bh1[lane];
    for (int k = 0; k < 32; k++)
        acc += g_pool[g * 32 + k] * inv * Wh1[k * 32 + lane];
    for (int k = 0; k < 12; k++)
        acc += meta[g * 12 + k] * Wh1[(32 + k) * 32 + lane];
    acc = acc > 0.f ? acc : 0.f;
    float r = acc * Wh2[lane];
#pragma unroll
    for (int off = 16; off; off >>= 1)
        r += __shfl_xor_sync(0xffffffffu, r, off);
    if (lane == 0) out[g] = r + bh2[0];
}

// ---------------- host ------------------------------------------------------
extern "C" void kernel_launch(void* const* d_in, const int* in_sizes, int n_in,
                              void* d_out, int out_size) {
    const float* x     = (const float*)d_in[0];
    const void*  ei    = d_in[1];
    const void*  batch = d_in[2];
    const float* meta  = (const float*)d_in[3];

    const float *Wl[3], *bl[3], *Wr[3], *br[3], *att[3], *bo[3];
    for (int l = 0; l < 3; l++) {
        int base = 4 + 6 * l;
        Wl[l]  = (const float*)d_in[base + 0];
        bl[l]  = (const float*)d_in[base + 1];
        Wr[l]  = (const float*)d_in[base + 2];
        br[l]  = (const float*)d_in[base + 3];
        att[l] = (const float*)d_in[base + 4];
        bo[l]  = (const float*)d_in[base + 5];
    }
    const float* Wh1 = (const float*)d_in[22];
    const float* bh1 = (const float*)d_in[23];
    const float* Wh2 = (const float*)d_in[24];
    const float* bh2 = (const float*)d_in[25];

    int N = in_sizes[0] / 128;
    int E = in_sizes[1] / 2;
    int ET = E + N;
    int B = in_sizes[3] / 12;
    float* out = (float*)d_out;

    float *p_xl, *p_xr, *p_h;
    cudaGetSymbolAddress((void**)&p_xl, g_xl);
    cudaGetSymbolAddress((void**)&p_xr, g_xr);
    cudaGetSymbolAddress((void**)&p_h, g_h);

    int g8 = (N + 7) / 8;
    int g64 = (N + 63) / 64;
    int node_blocks = (N * 32 + 255) / 256;
    int pack128_blocks = (2 * 32 * 128 + 255) / 256;
    int pack32_blocks = (2 * 32 * 32 + 255) / 256;

    // ---- prolog + layer-0 GEMM early (independent of CSR; also puts the
    //      dual GEMM in ncu's fixed capture slot)
    detect_kernel<<<1, 256>>>(ei);
    convert_kernel<<<(ET + 255) / 256, 256>>>(ei, batch, E, N);
    pack_w_kernel<<<pack128_blocks, 256>>>(Wl[0], Wr[0], 128);
    gemm128_dual_kernel<<<g8, 128>>>(x, bl[0], br[0], p_xl, p_xr, N);

    // ---- CSR build (once; graph shared by all layers)
    hist_kernel<<<(ET + 255) / 256, 256>>>(ET);
    int nb = (N + SCAN_BLK - 1) / SCAN_BLK;
    scan1_kernel<<<nb, SCAN_BLK>>>(N);
    scan2_kernel<<<1, SCAN_BLK>>>(nb);
    scan3_kernel<<<(N + 255) / 256, 256>>>(N);
    scatter_kernel<<<(ET + 255) / 256, 256>>>(ET);
    pool_init_kernel<<<(B * 32 + 255) / 256, 256>>>(B);

    // ---- layer 0 attention
    gat_node4_kernel<<<node_blocks, 256>>>(att[0], bo[0], N);

    // ---- layer 1
    pack_w_kernel<<<pack128_blocks, 256>>>(Wl[1], Wr[1], 128);
    gemm128_dual_kernel<<<g8, 128>>>(p_h, bl[1], br[1], p_xl, p_xr, N);
    gat_node4_kernel<<<node_blocks, 256>>>(att[1], bo[1], N);

    // ---- layer 2: H=1, DOUT=32, pool fused into epilogue
    pack_w_kernel<<<pack32_blocks, 256>>>(Wl[2], Wr[2], 32);
    gemm32_dual_kernel<<<g64, 128>>>(p_h, bl[2], br[2], p_xl, p_xr, N);
    gat_node1_kernel<<<node_blocks, 256>>>(att[2], bo[2], N);

    // ---- MLP head
    head_kernel<<<(B * 32 + 255) / 256, 256>>>(meta, Wh1, bh1, Wh2, bh2, out, B);
}

// round 9
// speedup vs baseline: 3.0111x; 1.4033x over previous
#include <cuda_runtime.h>
#include <math.h>

#define NMAX 50000
#define EMAX 800000
#define ETMAX (NMAX + EMAX)
#define BMAX 512
#define SCAN_BLK 256

// ---------------- scratch (device globals; no allocations allowed) ----------
__device__ float g_xl[NMAX * 128];
__device__ float g_xr[NMAX * 128];
__device__ float g_h[NMAX * 128];
__device__ int   g_src[ETMAX];
__device__ int   g_dst[ETMAX];
__device__ int   g_csrc[ETMAX];      // src node per dst-sorted edge
__device__ int   g_deg[NMAX];
__device__ int   g_scan[NMAX];
__device__ int   g_bsum[SCAN_BLK];
__device__ int   g_rowptr[NMAX + 1];
__device__ int   g_cursor[NMAX];
__device__ int   g_batch[NMAX];
__device__ float g_pool[BMAX * 32];
__device__ float g_cnt[BMAX];
__device__ int   g_is64;
// packed weights: wp[kk][col] = ulonglong2{(W[4kk],W[4kk+1]),(W[4kk+2],W[4kk+3])}
__device__ ulonglong2 g_wpl[32 * 128];
__device__ ulonglong2 g_wpr[32 * 128];

// ---------------- f32x2 packed math helpers ---------------------------------
__device__ __forceinline__ unsigned long long pack2(float lo, float hi) {
    unsigned long long r;
    asm("mov.b64 %0, {%1, %2};" : "=l"(r) : "f"(lo), "f"(hi));
    return r;
}
__device__ __forceinline__ void fma2(unsigned long long& acc,
                                     unsigned long long a,
                                     unsigned long long b) {
    asm("fma.rn.f32x2 %0, %1, %2, %0;" : "+l"(acc) : "l"(a), "l"(b));
}
__device__ __forceinline__ float hsum2(unsigned long long v) {
    float lo, hi;
    asm("mov.b64 {%0, %1}, %2;" : "=f"(lo), "=f"(hi) : "l"(v));
    return lo + hi;
}

// ---------------- dtype sniff: int64 vs int32 edge_index --------------------
__global__ void detect_kernel(const void* ei) {
    __shared__ int s;
    if (threadIdx.x == 0) s = 0;
    __syncthreads();
    const int* w = (const int*)ei;
    int v = w[2 * threadIdx.x + 1];
    atomicOr(&s, v);
    __syncthreads();
    if (threadIdx.x == 0) g_is64 = (s == 0) ? 1 : 0;
}

// Convert edge_index (+ self loops) and batch to int32; zero degree counters.
__global__ void convert_kernel(const void* ei, const void* batch, int E, int N) {
    int i = blockIdx.x * blockDim.x + threadIdx.x;
    int is64 = g_is64;
    if (i < E) {
        int s, d;
        if (is64) {
            const long long* p = (const long long*)ei;
            s = (int)p[i]; d = (int)p[(long long)E + i];
        } else {
            const int* p = (const int*)ei;
            s = p[i]; d = p[E + i];
        }
        g_src[i] = s; g_dst[i] = d;
    } else if (i < E + N) {
        int n = i - E;
        g_src[i] = n; g_dst[i] = n;
    }
    if (i < N) {
        g_batch[i] = is64 ? (int)((const long long*)batch)[i]
                          : ((const int*)batch)[i];
        g_deg[i] = 0;
    }
}

// ---------------- weight pre-pack -------------------------------------------
__global__ void pack_w_kernel(const float* __restrict__ Wl,
                              const float* __restrict__ Wr, int DOUT) {
    int i = blockIdx.x * blockDim.x + threadIdx.x;
    int tot = 32 * DOUT;
    if (i >= 2 * tot) return;
    const float* W = (i < tot) ? Wl : Wr;
    int j = (i < tot) ? i : i - tot;
    int kk = j / DOUT, col = j - kk * DOUT;
    ulonglong2 v;
    v.x = pack2(W[(4 * kk + 0) * DOUT + col], W[(4 * kk + 1) * DOUT + col]);
    v.y = pack2(W[(4 * kk + 2) * DOUT + col], W[(4 * kk + 3) * DOUT + col]);
    if (i < tot) g_wpl[j] = v; else g_wpr[j] = v;
}

// ---------------- CSR build: histogram -> scan -> scatter -------------------
__global__ void hist_kernel(int ET) {
    int i = blockIdx.x * blockDim.x + threadIdx.x;
    if (i < ET) atomicAdd(&g_deg[g_dst[i]], 1);
}

__global__ void scan1_kernel(int N) {
    __shared__ int sh[SCAN_BLK];
    int i = blockIdx.x * SCAN_BLK + threadIdx.x;
    int v = (i < N) ? g_deg[i] : 0;
    sh[threadIdx.x] = v;
    __syncthreads();
    for (int off = 1; off < SCAN_BLK; off <<= 1) {
        int t = (threadIdx.x >= off) ? sh[threadIdx.x - off] : 0;
        __syncthreads();
        sh[threadIdx.x] += t;
        __syncthreads();
    }
    if (i < N) g_scan[i] = sh[threadIdx.x];
    if (threadIdx.x == SCAN_BLK - 1) g_bsum[blockIdx.x] = sh[threadIdx.x];
}

__global__ void scan2_kernel(int nb) {
    __shared__ int sh[SCAN_BLK];
    int t = threadIdx.x;
    int v = (t < nb) ? g_bsum[t] : 0;
    sh[t] = v;
    __syncthreads();
    for (int off = 1; off < SCAN_BLK; off <<= 1) {
        int u = (t >= off) ? sh[t - off] : 0;
        __syncthreads();
        sh[t] += u;
        __syncthreads();
    }
    g_bsum[t] = sh[t] - v;  // exclusive
}

__global__ void scan3_kernel(int N) {
    int i = blockIdx.x * blockDim.x + threadIdx.x;
    if (i >= N) return;
    int incl = g_scan[i] + g_bsum[i >> 8];
    g_rowptr[i + 1] = incl;
    g_cursor[i] = incl - g_deg[i];
    if (i == 0) g_rowptr[0] = 0;
}

__global__ void scatter_kernel(int ET) {
    int i = blockIdx.x * blockDim.x + threadIdx.x;
    if (i >= ET) return;
    int d = g_dst[i];
    int pos = atomicAdd(&g_cursor[d], 1);
    g_csrc[pos] = g_src[i];
}

// ---------------- dual GEMM: Yl/Yr[N,128] = X[N,128] @ {Wl,Wr} + b ----------
// 128 threads (thread = output column for BOTH matrices), 16 rows per block:
// each W LDG.128 feeds 32 FFMA2; each X LDS.128 feeds 4 FFMA2.
__global__ void __launch_bounds__(128) gemm128_dual_kernel(
        const float* __restrict__ X,
        const float* __restrict__ bl,
        const float* __restrict__ br,
        float* __restrict__ Yl,
        float* __restrict__ Yr, int N) {
    __shared__ float4 sh[16 * 32];
    int n0 = blockIdx.x * 16;
    int tid = threadIdx.x;
    const float4* Xv = (const float4*)X;
    for (int i = tid; i < 16 * 32; i += 128) {
        int r = i >> 5, c = i & 31;
        int n = n0 + r;
        sh[i] = (n < N) ? Xv[(size_t)n * 32 + c] : make_float4(0.f, 0.f, 0.f, 0.f);
    }
    __syncthreads();
    unsigned long long accl[16], accr[16];
#pragma unroll
    for (int r = 0; r < 16; r++) { accl[r] = 0ull; accr[r] = 0ull; }
    const ulonglong2* shv = (const ulonglong2*)sh;
    for (int kk = 0; kk < 32; kk++) {
        ulonglong2 wl = g_wpl[kk * 128 + tid];
        ulonglong2 wr = g_wpr[kk * 128 + tid];
#pragma unroll
        for (int r = 0; r < 16; r++) {
            ulonglong2 xv = shv[r * 32 + kk];
            fma2(accl[r], xv.x, wl.x);
            fma2(accl[r], xv.y, wl.y);
            fma2(accr[r], xv.x, wr.x);
            fma2(accr[r], xv.y, wr.y);
        }
    }
    float bbl = bl[tid], bbr = br[tid];
#pragma unroll
    for (int r = 0; r < 16; r++) {
        int n = n0 + r;
        if (n < N) {
            Yl[(size_t)n * 128 + tid] = hsum2(accl[r]) + bbl;
            Yr[(size_t)n * 128 + tid] = hsum2(accr[r]) + bbr;
        }
    }
}

// dual GEMM DOUT=32: lane = column, 4 warps x 16 rows = 64 rows per block.
__global__ void gemm32_dual_kernel(const float* __restrict__ X,
                                   const float* __restrict__ bl,
                                   const float* __restrict__ br,
                                   float* __restrict__ Yl,
                                   float* __restrict__ Yr, int N) {
    __shared__ float4 sh[64 * 32];
    int n0 = blockIdx.x * 64;
    int tid = threadIdx.x;
    int warp = tid >> 5, lane = tid & 31;
    const float4* Xv = (const float4*)X;
    for (int i = tid; i < 64 * 32; i += 128) {
        int r = i >> 5, c = i & 31;
        int n = n0 + r;
        sh[i] = (n < N) ? Xv[(size_t)n * 32 + c] : make_float4(0.f, 0.f, 0.f, 0.f);
    }
    __syncthreads();
    unsigned long long accl[16], accr[16];
#pragma unroll
    for (int r = 0; r < 16; r++) { accl[r] = 0ull; accr[r] = 0ull; }
    const ulonglong2* shv = (const ulonglong2*)sh;
#pragma unroll 2
    for (int kk = 0; kk < 32; kk++) {
        ulonglong2 wl = g_wpl[kk * 32 + lane];
        ulonglong2 wr = g_wpr[kk * 32 + lane];
#pragma unroll
        for (int r = 0; r < 16; r++) {
            ulonglong2 xv = shv[(warp * 16 + r) * 32 + kk];
            fma2(accl[r], xv.x, wl.x);
            fma2(accl[r], xv.y, wl.y);
            fma2(accr[r], xv.x, wr.x);
            fma2(accr[r], xv.y, wr.y);
        }
    }
    float bbl = bl[lane], bbr = br[lane];
#pragma unroll
    for (int r = 0; r < 16; r++) {
        int n = n0 + warp * 16 + r;
        if (n < N) {
            Yl[(size_t)n * 32 + lane] = hsum2(accl[r]) + bbl;
            Yr[(size_t)n * 32 + lane] = hsum2(accr[r]) + bbr;
        }
    }
}

// ---------------- node-kernel helpers ----------------------------------------
// leaky_relu(a + xr) dot att, per-lane partial over 4 channels.
__device__ __forceinline__ float edot4(float4 a, float4 xr, float4 at) {
    float t0 = a.x + xr.x; t0 = t0 > 0.f ? t0 : 0.2f * t0;
    float t1 = a.y + xr.y; t1 = t1 > 0.f ? t1 : 0.2f * t1;
    float t2 = a.z + xr.z; t2 = t2 > 0.f ? t2 : 0.2f * t2;
    float t3 = a.w + xr.w; t3 = t3 > 0.f ? t3 : 0.2f * t3;
    return t0 * at.x + t1 * at.y + t2 * at.z + t3 * at.w;
}
// online-softmax state update with edge value a and logit p.
__device__ __forceinline__ void osm_update(float& m, float& d, float4& acc,
                                           float p, float4 a) {
    if (p > m) {
        float sc = __expf(m - p);  // exp(-inf)=0 on first edge
        d *= sc;
        acc.x *= sc; acc.y *= sc; acc.z *= sc; acc.w *= sc;
        m = p;
    }
    float w = __expf(p - m);
    d += w;
    acc.x += w * a.x; acc.y += w * a.y; acc.z += w * a.z; acc.w += w * a.w;
}

// ---------------- fused GATv2 per-node kernel, H=4 ---------------------------
// Warp per dst node. Lane owns channels [4*lane, 4*lane+4) = head lane/8.
// Per edge: 1 LDG.128, 3 shfl (sum within 8-lane head group), per-lane online
// softmax state for its own head. Zero atomics.
__global__ void gat_node4_kernel(const float* __restrict__ att,
                                 const float* __restrict__ bias, int N) {
    int n = (blockIdx.x * blockDim.x + threadIdx.x) >> 5;
    int lane = threadIdx.x & 31;
    if (n >= N) return;

    float4 attv = __ldg((const float4*)att + lane);
    float4 xrv = *(const float4*)(g_xr + (size_t)n * 128 + 4 * lane);
    float m = -INFINITY, d = 0.f;
    float4 acc = make_float4(0.f, 0.f, 0.f, 0.f);

    int e = g_rowptr[n], end = g_rowptr[n + 1];
    for (; e + 1 < end; e += 2) {
        int s0 = g_csrc[e], s1 = g_csrc[e + 1];
        float4 a0 = *(const float4*)(g_xl + (size_t)s0 * 128 + 4 * lane);
        float4 a1 = *(const float4*)(g_xl + (size_t)s1 * 128 + 4 * lane);
        float p0 = edot4(a0, xrv, attv);
        float p1 = edot4(a1, xrv, attv);
        p0 += __shfl_xor_sync(0xffffffffu, p0, 1);
        p1 += __shfl_xor_sync(0xffffffffu, p1, 1);
        p0 += __shfl_xor_sync(0xffffffffu, p0, 2);
        p1 += __shfl_xor_sync(0xffffffffu, p1, 2);
        p0 += __shfl_xor_sync(0xffffffffu, p0, 4);
        p1 += __shfl_xor_sync(0xffffffffu, p1, 4);
        osm_update(m, d, acc, p0, a0);
        osm_update(m, d, acc, p1, a1);
    }
    if (e < end) {
        int s0 = g_csrc[e];
        float4 a0 = *(const float4*)(g_xl + (size_t)s0 * 128 + 4 * lane);
        float p0 = edot4(a0, xrv, attv);
        p0 += __shfl_xor_sync(0xffffffffu, p0, 1);
        p0 += __shfl_xor_sync(0xffffffffu, p0, 2);
        p0 += __shfl_xor_sync(0xffffffffu, p0, 4);
        osm_update(m, d, acc, p0, a0);
    }

    float inv = 1.f / (d + 1e-16f);
    float4 bi = __ldg((const float4*)bias + lane);
    float4 v;
    v.x = acc.x * inv + bi.x; v.x = v.x > 0.f ? v.x : (__expf(v.x) - 1.f);
    v.y = acc.y * inv + bi.y; v.y = v.y > 0.f ? v.y : (__expf(v.y) - 1.f);
    v.z = acc.z * inv + bi.z; v.z = v.z > 0.f ? v.z : (__expf(v.z) - 1.f);
    v.w = acc.w * inv + bi.w; v.w = v.w > 0.f ? v.w : (__expf(v.w) - 1.f);
    *(float4*)(g_h + (size_t)n * 128 + 4 * lane) = v;
}

// ---------------- fused GATv2 per-node kernel, H=1 + pooling -----------------
// Warp per dst node; 4 edges per iteration, one per 8-lane group (sublane sl
// owns channels [4sl, 4sl+4)). Per-group online softmax; flash-merge across
// groups at the end (scale factors forced to 1 when m == nm so empty groups
// contribute exact zeros).
__global__ void gat_node1_kernel(const float* __restrict__ att,
                                 const float* __restrict__ bias, int N) {
    int n = (blockIdx.x * blockDim.x + threadIdx.x) >> 5;
    int lane = threadIdx.x & 31;
    if (n >= N) return;
    int grp = lane >> 3, sl = lane & 7;

    float4 attv = __ldg((const float4*)att + sl);
    float4 xrv = *(const float4*)(g_xr + (size_t)n * 32 + 4 * sl);
    float m = -INFINITY, d = 0.f;
    float4 acc = make_float4(0.f, 0.f, 0.f, 0.f);

    int start = g_rowptr[n], end = g_rowptr[n + 1];
    for (int eb = start; eb < end; eb += 4) {
        int me = eb + grp;
        bool valid = me < end;
        int s = valid ? g_csrc[me] : g_csrc[eb];
        float4 a = *(const float4*)(g_xl + (size_t)s * 32 + 4 * sl);
        float p = edot4(a, xrv, attv);
        p += __shfl_xor_sync(0xffffffffu, p, 1);
        p += __shfl_xor_sync(0xffffffffu, p, 2);
        p += __shfl_xor_sync(0xffffffffu, p, 4);
        if (valid) osm_update(m, d, acc, p, a);
    }

    // merge the 4 group states (xor 8, then 16)
#pragma unroll
    for (int off = 8; off <= 16; off <<= 1) {
        float mo = __shfl_xor_sync(0xffffffffu, m, off);
        float do_ = __shfl_xor_sync(0xffffffffu, d, off);
        float4 ao;
        ao.x = __shfl_xor_sync(0xffffffffu, acc.x, off);
        ao.y = __shfl_xor_sync(0xffffffffu, acc.y, off);
        ao.z = __shfl_xor_sync(0xffffffffu, acc.z, off);
        ao.w = __shfl_xor_sync(0xffffffffu, acc.w, off);
        float nm = fmaxf(m, mo);
        float s1 = (m == nm) ? 1.f : __expf(m - nm);
        float s2 = (mo == nm) ? 1.f : __expf(mo - nm);
        d = d * s1 + do_ * s2;
        acc.x = acc.x * s1 + ao.x * s2;
        acc.y = acc.y * s1 + ao.y * s2;
        acc.z = acc.z * s1 + ao.z * s2;
        acc.w = acc.w * s1 + ao.w * s2;
        m = nm;
    }

    if (grp == 0) {
        float inv = 1.f / (d + 1e-16f);
        float4 bi = __ldg((const float4*)bias + sl);
        float4 v;
        v.x = acc.x * inv + bi.x; v.x = v.x > 0.f ? v.x : (__expf(v.x) - 1.f);
        v.y = acc.y * inv + bi.y; v.y = v.y > 0.f ? v.y : (__expf(v.y) - 1.f);
        v.z = acc.z * inv + bi.z; v.z = v.z > 0.f ? v.z : (__expf(v.z) - 1.f);
        v.w = acc.w * inv + bi.w; v.w = v.w > 0.f ? v.w : (__expf(v.w) - 1.f);
        int b = g_batch[n];
        atomicAdd(&g_pool[b * 32 + 4 * sl + 0], v.x);
        atomicAdd(&g_pool[b * 32 + 4 * sl + 1], v.y);
        atomicAdd(&g_pool[b * 32 + 4 * sl + 2], v.z);
        atomicAdd(&g_pool[b * 32 + 4 * sl + 3], v.w);
        if (sl == 0) atomicAdd(&g_cnt[b], 1.f);
    }
}

// ---------------- pooling init + MLP head -----------------------------------
__global__ void pool_init_kernel(int B) {
    int i = blockIdx.x * blockDim.x + threadIdx.x;
    if (i < B * 32) g_pool[i] = 0.f;
    if (i < B) g_cnt[i] = 0.f;
}

__global__ void head_kernel(const float* __restrict__ meta,
                            const float* __restrict__ Wh1,
                            const float* __restrict__ bh1,
                            const float* __restrict__ Wh2,
                            const float* __restrict__ bh2,
                            float* __restrict__ out, int B) {
    int g = (blockIdx.x * blockDim.x + threadIdx.x) >> 5;
    int lane = threadIdx.x & 31;
    if (g >= B) return;
    float c = g_cnt[g];
    if (c < 1.f) c = 1.f;
    float inv = 1.f / c;
    float acc = bh1[lane];
    for (int k = 0; k < 32; k++)
        acc += g_pool[g * 32 + k] * inv * Wh1[k * 32 + lane];
    for (int k = 0; k < 12; k++)
        acc += meta[g * 12 + k] * Wh1[(32 + k) * 32 + lane];
    acc = acc > 0.f ? acc : 0.f;
    float r = acc * Wh2[lane];
#pragma unroll
    for (int off = 16; off; off >>= 1)
        r += __shfl_xor_sync(0xffffffffu, r, off);
    if (lane == 0) out[g] = r + bh2[0];
}

// ---------------- host ------------------------------------------------------
extern "C" void kernel_launch(void* const* d_in, const int* in_sizes, int n_in,
                              void* d_out, int out_size) {
    const float* x     = (const float*)d_in[0];
    const void*  ei    = d_in[1];
    const void*  batch = d_in[2];
    const float* meta  = (const float*)d_in[3];

    const float *Wl[3], *bl[3], *Wr[3], *br[3], *att[3], *bo[3];
    for (int l = 0; l < 3; l++) {
        int base = 4 + 6 * l;
        Wl[l]  = (const float*)d_in[base + 0];
        bl[l]  = (const float*)d_in[base + 1];
        Wr[l]  = (const float*)d_in[base + 2];
        br[l]  = (const float*)d_in[base + 3];
        att[l] = (const float*)d_in[base + 4];
        bo[l]  = (const float*)d_in[base + 5];
    }
    const float* Wh1 = (const float*)d_in[22];
    const float* bh1 = (const float*)d_in[23];
    const float* Wh2 = (const float*)d_in[24];
    const float* bh2 = (const float*)d_in[25];

    int N = in_sizes[0] / 128;
    int E = in_sizes[1] / 2;
    int ET = E + N;
    int B = in_sizes[3] / 12;
    float* out = (float*)d_out;

    float *p_xl, *p_xr, *p_h;
    cudaGetSymbolAddress((void**)&p_xl, g_xl);
    cudaGetSymbolAddress((void**)&p_xr, g_xr);
    cudaGetSymbolAddress((void**)&p_h, g_h);

    int g16 = (N + 15) / 16;
    int g64 = (N + 63) / 64;
    int node_blocks = (N * 32 + 255) / 256;
    int pack128_blocks = (2 * 32 * 128 + 255) / 256;
    int pack32_blocks = (2 * 32 * 32 + 255) / 256;

    // ---- prolog + layer-0 GEMM early (keeps dual GEMM in ncu capture slot)
    detect_kernel<<<1, 256>>>(ei);
    convert_kernel<<<(ET + 255) / 256, 256>>>(ei, batch, E, N);
    pack_w_kernel<<<pack128_blocks, 256>>>(Wl[0], Wr[0], 128);
    gemm128_dual_kernel<<<g16, 128>>>(x, bl[0], br[0], p_xl, p_xr, N);

    // ---- CSR build (once; graph shared by all layers)
    hist_kernel<<<(ET + 255) / 256, 256>>>(ET);
    int nb = (N + SCAN_BLK - 1) / SCAN_BLK;
    scan1_kernel<<<nb, SCAN_BLK>>>(N);
    scan2_kernel<<<1, SCAN_BLK>>>(nb);
    scan3_kernel<<<(N + 255) / 256, 256>>>(N);
    scatter_kernel<<<(ET + 255) / 256, 256>>>(ET);
    pool_init_kernel<<<(B * 32 + 255) / 256, 256>>>(B);

    // ---- layer 0 attention
    gat_node4_kernel<<<node_blocks, 256>>>(att[0], bo[0], N);

    // ---- layer 1
    pack_w_kernel<<<pack128_blocks, 256>>>(Wl[1], Wr[1], 128);
    gemm128_dual_kernel<<<g16, 128>>>(p_h, bl[1], br[1], p_xl, p_xr, N);
    gat_node4_kernel<<<node_blocks, 256>>>(att[1], bo[1], N);

    // ---- layer 2: H=1, DOUT=32, pool fused into epilogue
    pack_w_kernel<<<pack32_blocks, 256>>>(Wl[2], Wr[2], 32);
    gemm32_dual_kernel<<<g64, 128>>>(p_h, bl[2], br[2], p_xl, p_xr, N);
    gat_node1_kernel<<<node_blocks, 256>>>(att[2], bo[2], N);

    // ---- MLP head
    head_kernel<<<(B * 32 + 255) / 256, 256>>>(meta, Wh1, bh1, Wh2, bh2, out, B);
}

// round 13
// speedup vs baseline: 3.2050x; 1.0644x over previous
#include <cuda_runtime.h>
#include <math.h>

#define NMAX 50000
#define EMAX 800000
#define ETMAX (NMAX + EMAX)
#define BMAX 512
#define SCAN_BLK 256

// ---------------- scratch (device globals; no allocations allowed) ----------
__device__ float g_xl[NMAX * 128];
__device__ float g_xr[NMAX * 128];
__device__ float g_h[NMAX * 128];
__device__ int   g_src[ETMAX];
__device__ int   g_dst[ETMAX];
__device__ int   g_csrc[ETMAX];      // src node per dst-sorted edge
__device__ int   g_deg[NMAX];
__device__ int   g_scan[NMAX];
__device__ int   g_bsum[SCAN_BLK];
__device__ int   g_rowptr[NMAX + 1];
__device__ int   g_cursor[NMAX];
__device__ int   g_batch[NMAX];
__device__ float g_pool[BMAX * 32];
__device__ float g_cnt[BMAX];
__device__ int   g_is64;
// packed weights: wp[kk][col] = ulonglong2{(W[4kk],W[4kk+1]),(W[4kk+2],W[4kk+3])}
__device__ ulonglong2 g_wpl[32 * 128];
__device__ ulonglong2 g_wpr[32 * 128];

// ---------------- f32x2 packed math helpers ---------------------------------
__device__ __forceinline__ unsigned long long pack2(float lo, float hi) {
    unsigned long long r;
    asm("mov.b64 %0, {%1, %2};" : "=l"(r) : "f"(lo), "f"(hi));
    return r;
}
__device__ __forceinline__ void fma2(unsigned long long& acc,
                                     unsigned long long a,
                                     unsigned long long b) {
    asm("fma.rn.f32x2 %0, %1, %2, %0;" : "+l"(acc) : "l"(a), "l"(b));
}
__device__ __forceinline__ float hsum2(unsigned long long v) {
    float lo, hi;
    asm("mov.b64 {%0, %1}, %2;" : "=f"(lo), "=f"(hi) : "l"(v));
    return lo + hi;
}

// ---------------- dtype sniff: int64 vs int32 edge_index --------------------
__global__ void detect_kernel(const void* ei) {
    __shared__ int s;
    if (threadIdx.x == 0) s = 0;
    __syncthreads();
    const int* w = (const int*)ei;
    int v = w[2 * threadIdx.x + 1];
    atomicOr(&s, v);
    __syncthreads();
    if (threadIdx.x == 0) g_is64 = (s == 0) ? 1 : 0;
}

// Zero degree counters (must run before convert's fused histogram).
__global__ void zero_deg_kernel(int N) {
    int i = blockIdx.x * blockDim.x + threadIdx.x;
    if (i < N) g_deg[i] = 0;
}

// Convert edge_index (+ self loops) and batch to int32; fused degree histogram.
__global__ void convert_kernel(const void* ei, const void* batch, int E, int N) {
    int i = blockIdx.x * blockDim.x + threadIdx.x;
    int is64 = g_is64;
    if (i < E) {
        int s, d;
        if (is64) {
            const long long* p = (const long long*)ei;
            s = (int)p[i]; d = (int)p[(long long)E + i];
        } else {
            const int* p = (const int*)ei;
            s = p[i]; d = p[E + i];
        }
        g_src[i] = s; g_dst[i] = d;
        atomicAdd(&g_deg[d], 1);
    } else if (i < E + N) {
        int n = i - E;
        g_src[i] = n; g_dst[i] = n;
        atomicAdd(&g_deg[n], 1);
    }
    if (i < N) {
        g_batch[i] = is64 ? (int)((const long long*)batch)[i]
                          : ((const int*)batch)[i];
    }
}

// ---------------- weight pre-pack -------------------------------------------
__global__ void pack_w_kernel(const float* __restrict__ Wl,
                              const float* __restrict__ Wr, int DOUT) {
    int i = blockIdx.x * blockDim.x + threadIdx.x;
    int tot = 32 * DOUT;
    if (i >= 2 * tot) return;
    const float* W = (i < tot) ? Wl : Wr;
    int j = (i < tot) ? i : i - tot;
    int kk = j / DOUT, col = j - kk * DOUT;
    ulonglong2 v;
    v.x = pack2(W[(4 * kk + 0) * DOUT + col], W[(4 * kk + 1) * DOUT + col]);
    v.y = pack2(W[(4 * kk + 2) * DOUT + col], W[(4 * kk + 3) * DOUT + col]);
    if (i < tot) g_wpl[j] = v; else g_wpr[j] = v;
}

// ---------------- CSR build: scan -> scatter --------------------------------
__global__ void scan1_kernel(int N) {
    __shared__ int sh[SCAN_BLK];
    int i = blockIdx.x * SCAN_BLK + threadIdx.x;
    int v = (i < N) ? g_deg[i] : 0;
    sh[threadIdx.x] = v;
    __syncthreads();
    for (int off = 1; off < SCAN_BLK; off <<= 1) {
        int t = (threadIdx.x >= off) ? sh[threadIdx.x - off] : 0;
        __syncthreads();
        sh[threadIdx.x] += t;
        __syncthreads();
    }
    if (i < N) g_scan[i] = sh[threadIdx.x];
    if (threadIdx.x == SCAN_BLK - 1) g_bsum[blockIdx.x] = sh[threadIdx.x];
}

__global__ void scan2_kernel(int nb) {
    __shared__ int sh[SCAN_BLK];
    int t = threadIdx.x;
    int v = (t < nb) ? g_bsum[t] : 0;
    sh[t] = v;
    __syncthreads();
    for (int off = 1; off < SCAN_BLK; off <<= 1) {
        int u = (t >= off) ? sh[t - off] : 0;
        __syncthreads();
        sh[t] += u;
        __syncthreads();
    }
    g_bsum[t] = sh[t] - v;  // exclusive
}

__global__ void scan3_kernel(int N) {
    int i = blockIdx.x * blockDim.x + threadIdx.x;
    if (i >= N) return;
    int incl = g_scan[i] + g_bsum[i >> 8];
    g_rowptr[i + 1] = incl;
    g_cursor[i] = incl - g_deg[i];
    if (i == 0) g_rowptr[0] = 0;
}

__global__ void scatter_kernel(int ET) {
    int i = blockIdx.x * blockDim.x + threadIdx.x;
    if (i >= ET) return;
    int d = g_dst[i];
    int pos = atomicAdd(&g_cursor[d], 1);
    g_csrc[pos] = g_src[i];
}

// ---------------- dual GEMM: Yl/Yr[N,128] = X[N,128] @ {Wl,Wr} + b ----------
// 64 threads, each owning columns {tid, tid+64} of BOTH matrices; 8 rows per
// block. Each X LDS.128 feeds 8 FFMA2; per kk: 8 LDS + 4 LDG + 64 FFMA2.
__global__ void __launch_bounds__(64) gemm128_dual_kernel(
        const float* __restrict__ X,
        const float* __restrict__ bl,
        const float* __restrict__ br,
        float* __restrict__ Yl,
        float* __restrict__ Yr, int N) {
    __shared__ float4 sh[8 * 32];
    int n0 = blockIdx.x * 8;
    int tid = threadIdx.x;
    int c0 = tid, c1 = tid + 64;
    const float4* Xv = (const float4*)X;
    for (int i = tid; i < 8 * 32; i += 64) {
        int r = i >> 5, c = i & 31;
        int n = n0 + r;
        sh[i] = (n < N) ? Xv[(size_t)n * 32 + c] : make_float4(0.f, 0.f, 0.f, 0.f);
    }
    __syncthreads();
    unsigned long long al0[8], al1[8], ar0[8], ar1[8];
#pragma unroll
    for (int r = 0; r < 8; r++) { al0[r] = al1[r] = ar0[r] = ar1[r] = 0ull; }
    const ulonglong2* shv = (const ulonglong2*)sh;
    for (int kk = 0; kk < 32; kk++) {
        ulonglong2 wl0 = g_wpl[kk * 128 + c0];
        ulonglong2 wl1 = g_wpl[kk * 128 + c1];
        ulonglong2 wr0 = g_wpr[kk * 128 + c0];
        ulonglong2 wr1 = g_wpr[kk * 128 + c1];
#pragma unroll
        for (int r = 0; r < 8; r++) {
            ulonglong2 xv = shv[r * 32 + kk];
            fma2(al0[r], xv.x, wl0.x); fma2(al0[r], xv.y, wl0.y);
            fma2(al1[r], xv.x, wl1.x); fma2(al1[r], xv.y, wl1.y);
            fma2(ar0[r], xv.x, wr0.x); fma2(ar0[r], xv.y, wr0.y);
            fma2(ar1[r], xv.x, wr1.x); fma2(ar1[r], xv.y, wr1.y);
        }
    }
    float bl0 = bl[c0], bl1 = bl[c1], br0 = br[c0], br1 = br[c1];
#pragma unroll
    for (int r = 0; r < 8; r++) {
        int n = n0 + r;
        if (n < N) {
            Yl[(size_t)n * 128 + c0] = hsum2(al0[r]) + bl0;
            Yl[(size_t)n * 128 + c1] = hsum2(al1[r]) + bl1;
            Yr[(size_t)n * 128 + c0] = hsum2(ar0[r]) + br0;
            Yr[(size_t)n * 128 + c1] = hsum2(ar1[r]) + br1;
        }
    }
}

// dual GEMM DOUT=32: lane = column, 4 warps x 16 rows = 64 rows per block.
__global__ void gemm32_dual_kernel(const float* __restrict__ X,
                                   const float* __restrict__ bl,
                                   const float* __restrict__ br,
                                   float* __restrict__ Yl,
                                   float* __restrict__ Yr, int N) {
    __shared__ float4 sh[64 * 32];
    int n0 = blockIdx.x * 64;
    int tid = threadIdx.x;
    int warp = tid >> 5, lane = tid & 31;
    const float4* Xv = (const float4*)X;
    for (int i = tid; i < 64 * 32; i += 128) {
        int r = i >> 5, c = i & 31;
        int n = n0 + r;
        sh[i] = (n < N) ? Xv[(size_t)n * 32 + c] : make_float4(0.f, 0.f, 0.f, 0.f);
    }
    __syncthreads();
    unsigned long long accl[16], accr[16];
#pragma unroll
    for (int r = 0; r < 16; r++) { accl[r] = 0ull; accr[r] = 0ull; }
    const ulonglong2* shv = (const ulonglong2*)sh;
    for (int kk = 0; kk < 32; kk++) {
        ulonglong2 wl = g_wpl[kk * 32 + lane];
        ulonglong2 wr = g_wpr[kk * 32 + lane];
#pragma unroll
        for (int r = 0; r < 16; r++) {
            ulonglong2 xv = shv[(warp * 16 + r) * 32 + kk];
            fma2(accl[r], xv.x, wl.x);
            fma2(accl[r], xv.y, wl.y);
            fma2(accr[r], xv.x, wr.x);
            fma2(accr[r], xv.y, wr.y);
        }
    }
    float bbl = bl[lane], bbr = br[lane];
#pragma unroll
    for (int r = 0; r < 16; r++) {
        int n = n0 + warp * 16 + r;
        if (n < N) {
            Yl[(size_t)n * 32 + lane] = hsum2(accl[r]) + bbl;
            Yr[(size_t)n * 32 + lane] = hsum2(accr[r]) + bbr;
        }
    }
}

// ---------------- node-kernel helpers ----------------------------------------
__device__ __forceinline__ float edot4(float4 a, float4 xr, float4 at) {
    float t0 = a.x + xr.x; t0 = t0 > 0.f ? t0 : 0.2f * t0;
    float t1 = a.y + xr.y; t1 = t1 > 0.f ? t1 : 0.2f * t1;
    float t2 = a.z + xr.z; t2 = t2 > 0.f ? t2 : 0.2f * t2;
    float t3 = a.w + xr.w; t3 = t3 > 0.f ? t3 : 0.2f * t3;
    return t0 * at.x + t1 * at.y + t2 * at.z + t3 * at.w;
}
__device__ __forceinline__ void osm_update(float& m, float& d, float4& acc,
                                           float p, float4 a) {
    if (p > m) {
        float sc = __expf(m - p);  // exp(-inf)=0 on first edge
        d *= sc;
        acc.x *= sc; acc.y *= sc; acc.z *= sc; acc.w *= sc;
        m = p;
    }
    float w = __expf(p - m);
    d += w;
    acc.x += w * a.x; acc.y += w * a.y; acc.z += w * a.z; acc.w += w * a.w;
}

// ---------------- fused GATv2 per-node kernel, H=4 ---------------------------
// Warp per dst node. Lane owns channels [4*lane, 4*lane+4) = head lane/8.
// Per edge: 1 LDG.128, 3 shfl, per-lane online softmax state. Zero atomics.
__global__ void gat_node4_kernel(const float* __restrict__ att,
                                 const float* __restrict__ bias, int N) {
    int n = (blockIdx.x * blockDim.x + threadIdx.x) >> 5;
    int lane = threadIdx.x & 31;
    if (n >= N) return;

    float4 attv = __ldg((const float4*)att + lane);
    float4 xrv = *(const float4*)(g_xr + (size_t)n * 128 + 4 * lane);
    float m = -INFINITY, d = 0.f;
    float4 acc = make_float4(0.f, 0.f, 0.f, 0.f);

    int e = g_rowptr[n], end = g_rowptr[n + 1];
    for (; e + 1 < end; e += 2) {
        int s0 = g_csrc[e], s1 = g_csrc[e + 1];
        float4 a0 = *(const float4*)(g_xl + (size_t)s0 * 128 + 4 * lane);
        float4 a1 = *(const float4*)(g_xl + (size_t)s1 * 128 + 4 * lane);
        float p0 = edot4(a0, xrv, attv);
        float p1 = edot4(a1, xrv, attv);
        p0 += __shfl_xor_sync(0xffffffffu, p0, 1);
        p1 += __shfl_xor_sync(0xffffffffu, p1, 1);
        p0 += __shfl_xor_sync(0xffffffffu, p0, 2);
        p1 += __shfl_xor_sync(0xffffffffu, p1, 2);
        p0 += __shfl_xor_sync(0xffffffffu, p0, 4);
        p1 += __shfl_xor_sync(0xffffffffu, p1, 4);
        osm_update(m, d, acc, p0, a0);
        osm_update(m, d, acc, p1, a1);
    }
    if (e < end) {
        int s0 = g_csrc[e];
        float4 a0 = *(const float4*)(g_xl + (size_t)s0 * 128 + 4 * lane);
        float p0 = edot4(a0, xrv, attv);
        p0 += __shfl_xor_sync(0xffffffffu, p0, 1);
        p0 += __shfl_xor_sync(0xffffffffu, p0, 2);
        p0 += __shfl_xor_sync(0xffffffffu, p0, 4);
        osm_update(m, d, acc, p0, a0);
    }

    float inv = 1.f / (d + 1e-16f);
    float4 bi = __ldg((const float4*)bias + lane);
    float4 v;
    v.x = acc.x * inv + bi.x; v.x = v.x > 0.f ? v.x : (__expf(v.x) - 1.f);
    v.y = acc.y * inv + bi.y; v.y = v.y > 0.f ? v.y : (__expf(v.y) - 1.f);
    v.z = acc.z * inv + bi.z; v.z = v.z > 0.f ? v.z : (__expf(v.z) - 1.f);
    v.w = acc.w * inv + bi.w; v.w = v.w > 0.f ? v.w : (__expf(v.w) - 1.f);
    *(float4*)(g_h + (size_t)n * 128 + 4 * lane) = v;
}

// ---------------- fused GATv2 per-node kernel, H=1 + pooling -----------------
__global__ void gat_node1_kernel(const float* __restrict__ att,
                                 const float* __restrict__ bias, int N) {
    int n = (blockIdx.x * blockDim.x + threadIdx.x) >> 5;
    int lane = threadIdx.x & 31;
    if (n >= N) return;
    int grp = lane >> 3, sl = lane & 7;

    float4 attv = __ldg((const float4*)att + sl);
    float4 xrv = *(const float4*)(g_xr + (size_t)n * 32 + 4 * sl);
    float m = -INFINITY, d = 0.f;
    float4 acc = make_float4(0.f, 0.f, 0.f, 0.f);

    int start = g_rowptr[n], end = g_rowptr[n + 1];
    for (int eb = start; eb < end; eb += 4) {
        int me = eb + grp;
        bool valid = me < end;
        int s = valid ? g_csrc[me] : g_csrc[eb];
        float4 a = *(const float4*)(g_xl + (size_t)s * 32 + 4 * sl);
        float p = edot4(a, xrv, attv);
        p += __shfl_xor_sync(0xffffffffu, p, 1);
        p += __shfl_xor_sync(0xffffffffu, p, 2);
        p += __shfl_xor_sync(0xffffffffu, p, 4);
        if (valid) osm_update(m, d, acc, p, a);
    }

    // merge the 4 group states (xor 8, then 16)
#pragma unroll
    for (int off = 8; off <= 16; off <<= 1) {
        float mo = __shfl_xor_sync(0xffffffffu, m, off);
        float do_ = __shfl_xor_sync(0xffffffffu, d, off);
        float4 ao;
        ao.x = __shfl_xor_sync(0xffffffffu, acc.x, off);
        ao.y = __shfl_xor_sync(0xffffffffu, acc.y, off);
        ao.z = __shfl_xor_sync(0xffffffffu, acc.z, off);
        ao.w = __shfl_xor_sync(0xffffffffu, acc.w, off);
        float nm = fmaxf(m, mo);
        float s1 = (m == nm) ? 1.f : __expf(m - nm);
        float s2 = (mo == nm) ? 1.f : __expf(mo - nm);
        d = d * s1 + do_ * s2;
        acc.x = acc.x * s1 + ao.x * s2;
        acc.y = acc.y * s1 + ao.y * s2;
        acc.z = acc.z * s1 + ao.z * s2;
        acc.w = acc.w * s1 + ao.w * s2;
        m = nm;
    }

    if (grp == 0) {
        float inv = 1.f / (d + 1e-16f);
        float4 bi = __ldg((const float4*)bias + sl);
        float4 v;
        v.x = acc.x * inv + bi.x; v.x = v.x > 0.f ? v.x : (__expf(v.x) - 1.f);
        v.y = acc.y * inv + bi.y; v.y = v.y > 0.f ? v.y : (__expf(v.y) - 1.f);
        v.z = acc.z * inv + bi.z; v.z = v.z > 0.f ? v.z : (__expf(v.z) - 1.f);
        v.w = acc.w * inv + bi.w; v.w = v.w > 0.f ? v.w : (__expf(v.w) - 1.f);
        int b = g_batch[n];
        atomicAdd(&g_pool[b * 32 + 4 * sl + 0], v.x);
        atomicAdd(&g_pool[b * 32 + 4 * sl + 1], v.y);
        atomicAdd(&g_pool[b * 32 + 4 * sl + 2], v.z);
        atomicAdd(&g_pool[b * 32 + 4 * sl + 3], v.w);
        if (sl == 0) atomicAdd(&g_cnt[b], 1.f);
    }
}

// ---------------- pooling init + MLP head -----------------------------------
__global__ void pool_init_kernel(int B) {
    int i = blockIdx.x * blockDim.x + threadIdx.x;
    if (i < B * 32) g_pool[i] = 0.f;
    if (i < B) g_cnt[i] = 0.f;
}

__global__ void head_kernel(const float* __restrict__ meta,
                            const float* __restrict__ Wh1,
                            const float* __restrict__ bh1,
                            const float* __restrict__ Wh2,
                            const float* __restrict__ bh2,
                            float* __restrict__ out, int B) {
    int g = (blockIdx.x * blockDim.x + threadIdx.x) >> 5;
    int lane = threadIdx.x & 31;
    if (g >= B) return;
    float c = g_cnt[g];
    if (c < 1.f) c = 1.f;
    float inv = 1.f / c;
    float acc = bh1[lane];
    for (int k = 0; k < 32; k++)
        acc += g_pool[g * 32 + k] * inv * Wh1[k * 32 + lane];
    for (int k = 0; k < 12; k++)
        acc += meta[g * 12 + k] * Wh1[(32 + k) * 32 + lane];
    acc = acc > 0.f ? acc : 0.f;
    float r = acc * Wh2[lane];
#pragma unroll
    for (int off = 16; off; off >>= 1)
        r += __shfl_xor_sync(0xffffffffu, r, off);
    if (lane == 0) out[g] = r + bh2[0];
}

// ---------------- host ------------------------------------------------------
extern "C" void kernel_launch(void* const* d_in, const int* in_sizes, int n_in,
                              void* d_out, int out_size) {
    const float* x     = (const float*)d_in[0];
    const void*  ei    = d_in[1];
    const void*  batch = d_in[2];
    const float* meta  = (const float*)d_in[3];

    const float *Wl[3], *bl[3], *Wr[3], *br[3], *att[3], *bo[3];
    for (int l = 0; l < 3; l++) {
        int base = 4 + 6 * l;
        Wl[l]  = (const float*)d_in[base + 0];
        bl[l]  = (const float*)d_in[base + 1];
        Wr[l]  = (const float*)d_in[base + 2];
        br[l]  = (const float*)d_in[base + 3];
        att[l] = (const float*)d_in[base + 4];
        bo[l]  = (const float*)d_in[base + 5];
    }
    const float* Wh1 = (const float*)d_in[22];
    const float* bh1 = (const float*)d_in[23];
    const float* Wh2 = (const float*)d_in[24];
    const float* bh2 = (const float*)d_in[25];

    int N = in_sizes[0] / 128;
    int E = in_sizes[1] / 2;
    int ET = E + N;
    int B = in_sizes[3] / 12;
    float* out = (float*)d_out;

    float *p_xl, *p_xr, *p_h;
    cudaGetSymbolAddress((void**)&p_xl, g_xl);
    cudaGetSymbolAddress((void**)&p_xr, g_xr);
    cudaGetSymbolAddress((void**)&p_h, g_h);

    int g8 = (N + 7) / 8;
    int g64 = (N + 63) / 64;
    int node_blocks = (N * 32 + 255) / 256;
    int pack128_blocks = (2 * 32 * 128 + 255) / 256;
    int pack32_blocks = (2 * 32 * 32 + 255) / 256;

    // ---- prolog + layer-0 GEMM early (keeps dual GEMM in ncu capture slot)
    detect_kernel<<<1, 256>>>(ei);
    zero_deg_kernel<<<(N + 255) / 256, 256>>>(N);
    convert_kernel<<<(ET + 255) / 256, 256>>>(ei, batch, E, N);
    pack_w_kernel<<<pack128_blocks, 256>>>(Wl[0], Wr[0], 128);
    gemm128_dual_kernel<<<g8, 64>>>(x, bl[0], br[0], p_xl, p_xr, N);

    // ---- CSR build (once; graph shared by all layers)
    int nb = (N + SCAN_BLK - 1) / SCAN_BLK;
    scan1_kernel<<<nb, SCAN_BLK>>>(N);
    scan2_kernel<<<1, SCAN_BLK>>>(nb);
    scan3_kernel<<<(N + 255) / 256, 256>>>(N);
    scatter_kernel<<<(ET + 255) / 256, 256>>>(ET);
    pool_init_kernel<<<(B * 32 + 255) / 256, 256>>>(B);

    // ---- layer 0 attention
    gat_node4_kernel<<<node_blocks, 256>>>(att[0], bo[0], N);

    // ---- layer 1
    pack_w_kernel<<<pack128_blocks, 256>>>(Wl[1], Wr[1], 128);
    gemm128_dual_kernel<<<g8, 64>>>(p_h, bl[1], br[1], p_xl, p_xr, N);
    gat_node4_kernel<<<node_blocks, 256>>>(att[1], bo[1], N);

    // ---- layer 2: H=1, DOUT=32, pool fused into epilogue
    pack_w_kernel<<<pack32_blocks, 256>>>(Wl[2], Wr[2], 32);
    gemm32_dual_kernel<<<g64, 128>>>(p_h, bl[2], br[2], p_xl, p_xr, N);
    gat_node1_kernel<<<node_blocks, 256>>>(att[2], bo[2], N);

    // ---- MLP head
    head_kernel<<<(B * 32 + 255) / 256, 256>>>(meta, Wh1, bh1, Wh2, bh2, out, B);
}

// round 14
// speedup vs baseline: 3.2709x; 1.0206x over previous
#include <cuda_runtime.h>
#include <math.h>

#define NMAX 50000
#define EMAX 800000
#define ETMAX (NMAX + EMAX)
#define BMAX 512
#define SCAN_BLK 256

// ---------------- scratch (device globals; no allocations allowed) ----------
__device__ float g_xl[NMAX * 128];
__device__ float g_xr[NMAX * 128];
__device__ float g_h[NMAX * 128];
__device__ int   g_src[ETMAX];
__device__ int   g_dst[ETMAX];
__device__ int   g_csrc[ETMAX];      // src node per dst-sorted edge
__device__ int   g_deg[NMAX];
__device__ int   g_scan[NMAX];
__device__ int   g_bsum[SCAN_BLK];
__device__ int   g_rowptr[NMAX + 1];
__device__ int   g_cursor[NMAX];
__device__ int   g_batch[NMAX];
__device__ float g_pool[BMAX * 32];
__device__ float g_cnt[BMAX];
__device__ int   g_is64;
// packed weights: wp[kk][col] = ulonglong2{(W[4kk],W[4kk+1]),(W[4kk+2],W[4kk+3])}
__device__ ulonglong2 g_wpl[32 * 128];
__device__ ulonglong2 g_wpr[32 * 128];

// ---------------- f32x2 packed math helpers ---------------------------------
__device__ __forceinline__ unsigned long long pack2(float lo, float hi) {
    unsigned long long r;
    asm("mov.b64 %0, {%1, %2};" : "=l"(r) : "f"(lo), "f"(hi));
    return r;
}
__device__ __forceinline__ void fma2(unsigned long long& acc,
                                     unsigned long long a,
                                     unsigned long long b) {
    asm("fma.rn.f32x2 %0, %1, %2, %0;" : "+l"(acc) : "l"(a), "l"(b));
}
__device__ __forceinline__ float hsum2(unsigned long long v) {
    float lo, hi;
    asm("mov.b64 {%0, %1}, %2;" : "=f"(lo), "=f"(hi) : "l"(v));
    return lo + hi;
}

// ---------------- dtype sniff: int64 vs int32 edge_index --------------------
__global__ void detect_kernel(const void* ei) {
    __shared__ int s;
    if (threadIdx.x == 0) s = 0;
    __syncthreads();
    const int* w = (const int*)ei;
    int v = w[2 * threadIdx.x + 1];
    atomicOr(&s, v);
    __syncthreads();
    if (threadIdx.x == 0) g_is64 = (s == 0) ? 1 : 0;
}

// Zero degree counters (must run before convert's fused histogram).
__global__ void zero_deg_kernel(int N) {
    int i = blockIdx.x * blockDim.x + threadIdx.x;
    if (i < N) g_deg[i] = 0;
}

// Convert edge_index (+ self loops) and batch to int32; fused degree histogram.
__global__ void convert_kernel(const void* ei, const void* batch, int E, int N) {
    int i = blockIdx.x * blockDim.x + threadIdx.x;
    int is64 = g_is64;
    if (i < E) {
        int s, d;
        if (is64) {
            const long long* p = (const long long*)ei;
            s = (int)p[i]; d = (int)p[(long long)E + i];
        } else {
            const int* p = (const int*)ei;
            s = p[i]; d = p[E + i];
        }
        g_src[i] = s; g_dst[i] = d;
        atomicAdd(&g_deg[d], 1);
    } else if (i < E + N) {
        int n = i - E;
        g_src[i] = n; g_dst[i] = n;
        atomicAdd(&g_deg[n], 1);
    }
    if (i < N) {
        g_batch[i] = is64 ? (int)((const long long*)batch)[i]
                          : ((const int*)batch)[i];
    }
}

// ---------------- weight pre-pack -------------------------------------------
__global__ void pack_w_kernel(const float* __restrict__ Wl,
                              const float* __restrict__ Wr, int DOUT) {
    int i = blockIdx.x * blockDim.x + threadIdx.x;
    int tot = 32 * DOUT;
    if (i >= 2 * tot) return;
    const float* W = (i < tot) ? Wl : Wr;
    int j = (i < tot) ? i : i - tot;
    int kk = j / DOUT, col = j - kk * DOUT;
    ulonglong2 v;
    v.x = pack2(W[(4 * kk + 0) * DOUT + col], W[(4 * kk + 1) * DOUT + col]);
    v.y = pack2(W[(4 * kk + 2) * DOUT + col], W[(4 * kk + 3) * DOUT + col]);
    if (i < tot) g_wpl[j] = v; else g_wpr[j] = v;
}

// ---------------- CSR build: scan -> scatter --------------------------------
__global__ void scan1_kernel(int N) {
    __shared__ int sh[SCAN_BLK];
    int i = blockIdx.x * SCAN_BLK + threadIdx.x;
    int v = (i < N) ? g_deg[i] : 0;
    sh[threadIdx.x] = v;
    __syncthreads();
    for (int off = 1; off < SCAN_BLK; off <<= 1) {
        int t = (threadIdx.x >= off) ? sh[threadIdx.x - off] : 0;
        __syncthreads();
        sh[threadIdx.x] += t;
        __syncthreads();
    }
    if (i < N) g_scan[i] = sh[threadIdx.x];
    if (threadIdx.x == SCAN_BLK - 1) g_bsum[blockIdx.x] = sh[threadIdx.x];
}

__global__ void scan2_kernel(int nb) {
    __shared__ int sh[SCAN_BLK];
    int t = threadIdx.x;
    int v = (t < nb) ? g_bsum[t] : 0;
    sh[t] = v;
    __syncthreads();
    for (int off = 1; off < SCAN_BLK; off <<= 1) {
        int u = (t >= off) ? sh[t - off] : 0;
        __syncthreads();
        sh[t] += u;
        __syncthreads();
    }
    g_bsum[t] = sh[t] - v;  // exclusive
}

__global__ void scan3_kernel(int N) {
    int i = blockIdx.x * blockDim.x + threadIdx.x;
    if (i >= N) return;
    int incl = g_scan[i] + g_bsum[i >> 8];
    g_rowptr[i + 1] = incl;
    g_cursor[i] = incl - g_deg[i];
    if (i == 0) g_rowptr[0] = 0;
}

__global__ void scatter_kernel(int ET) {
    int i = blockIdx.x * blockDim.x + threadIdx.x;
    if (i >= ET) return;
    int d = g_dst[i];
    int pos = atomicAdd(&g_cursor[d], 1);
    g_csrc[pos] = g_src[i];
}

// ---------------- dual GEMM: Yl/Yr[N,128] = X[N,128] @ {Wl,Wr} + b ----------
// 64 threads, each owning columns {tid, tid+64} of BOTH matrices; 8 rows per
// block. kk loop unrolled 4x so ptxas batches the weight LDGs (16 in flight).
__global__ void __launch_bounds__(64) gemm128_dual_kernel(
        const float* __restrict__ X,
        const float* __restrict__ bl,
        const float* __restrict__ br,
        float* __restrict__ Yl,
        float* __restrict__ Yr, int N) {
    __shared__ float4 sh[8 * 32];
    int n0 = blockIdx.x * 8;
    int tid = threadIdx.x;
    int c0 = tid, c1 = tid + 64;
    const float4* Xv = (const float4*)X;
    for (int i = tid; i < 8 * 32; i += 64) {
        int r = i >> 5, c = i & 31;
        int n = n0 + r;
        sh[i] = (n < N) ? Xv[(size_t)n * 32 + c] : make_float4(0.f, 0.f, 0.f, 0.f);
    }
    __syncthreads();
    unsigned long long al0[8], al1[8], ar0[8], ar1[8];
#pragma unroll
    for (int r = 0; r < 8; r++) { al0[r] = al1[r] = ar0[r] = ar1[r] = 0ull; }
    const ulonglong2* shv = (const ulonglong2*)sh;
#pragma unroll 4
    for (int kk = 0; kk < 32; kk++) {
        ulonglong2 wl0 = g_wpl[kk * 128 + c0];
        ulonglong2 wl1 = g_wpl[kk * 128 + c1];
        ulonglong2 wr0 = g_wpr[kk * 128 + c0];
        ulonglong2 wr1 = g_wpr[kk * 128 + c1];
#pragma unroll
        for (int r = 0; r < 8; r++) {
            ulonglong2 xv = shv[r * 32 + kk];
            fma2(al0[r], xv.x, wl0.x); fma2(al0[r], xv.y, wl0.y);
            fma2(al1[r], xv.x, wl1.x); fma2(al1[r], xv.y, wl1.y);
            fma2(ar0[r], xv.x, wr0.x); fma2(ar0[r], xv.y, wr0.y);
            fma2(ar1[r], xv.x, wr1.x); fma2(ar1[r], xv.y, wr1.y);
        }
    }
    float bl0 = bl[c0], bl1 = bl[c1], br0 = br[c0], br1 = br[c1];
#pragma unroll
    for (int r = 0; r < 8; r++) {
        int n = n0 + r;
        if (n < N) {
            Yl[(size_t)n * 128 + c0] = hsum2(al0[r]) + bl0;
            Yl[(size_t)n * 128 + c1] = hsum2(al1[r]) + bl1;
            Yr[(size_t)n * 128 + c0] = hsum2(ar0[r]) + br0;
            Yr[(size_t)n * 128 + c1] = hsum2(ar1[r]) + br1;
        }
    }
}

// dual GEMM DOUT=32: lane = column, 4 warps x 16 rows = 64 rows per block.
__global__ void gemm32_dual_kernel(const float* __restrict__ X,
                                   const float* __restrict__ bl,
                                   const float* __restrict__ br,
                                   float* __restrict__ Yl,
                                   float* __restrict__ Yr, int N) {
    __shared__ float4 sh[64 * 32];
    int n0 = blockIdx.x * 64;
    int tid = threadIdx.x;
    int warp = tid >> 5, lane = tid & 31;
    const float4* Xv = (const float4*)X;
    for (int i = tid; i < 64 * 32; i += 128) {
        int r = i >> 5, c = i & 31;
        int n = n0 + r;
        sh[i] = (n < N) ? Xv[(size_t)n * 32 + c] : make_float4(0.f, 0.f, 0.f, 0.f);
    }
    __syncthreads();
    unsigned long long accl[16], accr[16];
#pragma unroll
    for (int r = 0; r < 16; r++) { accl[r] = 0ull; accr[r] = 0ull; }
    const ulonglong2* shv = (const ulonglong2*)sh;
#pragma unroll 4
    for (int kk = 0; kk < 32; kk++) {
        ulonglong2 wl = g_wpl[kk * 32 + lane];
        ulonglong2 wr = g_wpr[kk * 32 + lane];
#pragma unroll
        for (int r = 0; r < 16; r++) {
            ulonglong2 xv = shv[(warp * 16 + r) * 32 + kk];
            fma2(accl[r], xv.x, wl.x);
            fma2(accl[r], xv.y, wl.y);
            fma2(accr[r], xv.x, wr.x);
            fma2(accr[r], xv.y, wr.y);
        }
    }
    float bbl = bl[lane], bbr = br[lane];
#pragma unroll
    for (int r = 0; r < 16; r++) {
        int n = n0 + warp * 16 + r;
        if (n < N) {
            Yl[(size_t)n * 32 + lane] = hsum2(accl[r]) + bbl;
            Yr[(size_t)n * 32 + lane] = hsum2(accr[r]) + bbr;
        }
    }
}

// ---------------- node-kernel helpers ----------------------------------------
__device__ __forceinline__ float edot4(float4 a, float4 xr, float4 at) {
    float t0 = a.x + xr.x; t0 = t0 > 0.f ? t0 : 0.2f * t0;
    float t1 = a.y + xr.y; t1 = t1 > 0.f ? t1 : 0.2f * t1;
    float t2 = a.z + xr.z; t2 = t2 > 0.f ? t2 : 0.2f * t2;
    float t3 = a.w + xr.w; t3 = t3 > 0.f ? t3 : 0.2f * t3;
    return t0 * at.x + t1 * at.y + t2 * at.z + t3 * at.w;
}
__device__ __forceinline__ void osm_update(float& m, float& d, float4& acc,
                                           float p, float4 a) {
    if (p > m) {
        float sc = __expf(m - p);  // exp(-inf)=0 on first edge
        d *= sc;
        acc.x *= sc; acc.y *= sc; acc.z *= sc; acc.w *= sc;
        m = p;
    }
    float w = __expf(p - m);
    d += w;
    acc.x += w * a.x; acc.y += w * a.y; acc.z += w * a.z; acc.w += w * a.w;
}

// ---------------- fused GATv2 per-node kernel, H=4 ---------------------------
// Warp per dst node. Lane owns channels [4*lane, 4*lane+4) = head lane/8.
// 4 edges in flight per iteration: 4 LDG.128 up front, 4 interleaved shfl
// chains, then 4 online-softmax updates. Zero atomics.
__global__ void gat_node4_kernel(const float* __restrict__ att,
                                 const float* __restrict__ bias, int N) {
    int n = (blockIdx.x * blockDim.x + threadIdx.x) >> 5;
    int lane = threadIdx.x & 31;
    if (n >= N) return;

    float4 attv = __ldg((const float4*)att + lane);
    float4 xrv = *(const float4*)(g_xr + (size_t)n * 128 + 4 * lane);
    float m = -INFINITY, d = 0.f;
    float4 acc = make_float4(0.f, 0.f, 0.f, 0.f);

    int e = g_rowptr[n], end = g_rowptr[n + 1];
    for (; e + 3 < end; e += 4) {
        int s0 = g_csrc[e], s1 = g_csrc[e + 1];
        int s2 = g_csrc[e + 2], s3 = g_csrc[e + 3];
        float4 a0 = *(const float4*)(g_xl + (size_t)s0 * 128 + 4 * lane);
        float4 a1 = *(const float4*)(g_xl + (size_t)s1 * 128 + 4 * lane);
        float4 a2 = *(const float4*)(g_xl + (size_t)s2 * 128 + 4 * lane);
        float4 a3 = *(const float4*)(g_xl + (size_t)s3 * 128 + 4 * lane);
        float p0 = edot4(a0, xrv, attv);
        float p1 = edot4(a1, xrv, attv);
        float p2 = edot4(a2, xrv, attv);
        float p3 = edot4(a3, xrv, attv);
        p0 += __shfl_xor_sync(0xffffffffu, p0, 1);
        p1 += __shfl_xor_sync(0xffffffffu, p1, 1);
        p2 += __shfl_xor_sync(0xffffffffu, p2, 1);
        p3 += __shfl_xor_sync(0xffffffffu, p3, 1);
        p0 += __shfl_xor_sync(0xffffffffu, p0, 2);
        p1 += __shfl_xor_sync(0xffffffffu, p1, 2);
        p2 += __shfl_xor_sync(0xffffffffu, p2, 2);
        p3 += __shfl_xor_sync(0xffffffffu, p3, 2);
        p0 += __shfl_xor_sync(0xffffffffu, p0, 4);
        p1 += __shfl_xor_sync(0xffffffffu, p1, 4);
        p2 += __shfl_xor_sync(0xffffffffu, p2, 4);
        p3 += __shfl_xor_sync(0xffffffffu, p3, 4);
        osm_update(m, d, acc, p0, a0);
        osm_update(m, d, acc, p1, a1);
        osm_update(m, d, acc, p2, a2);
        osm_update(m, d, acc, p3, a3);
    }
    for (; e < end; e++) {
        int s0 = g_csrc[e];
        float4 a0 = *(const float4*)(g_xl + (size_t)s0 * 128 + 4 * lane);
        float p0 = edot4(a0, xrv, attv);
        p0 += __shfl_xor_sync(0xffffffffu, p0, 1);
        p0 += __shfl_xor_sync(0xffffffffu, p0, 2);
        p0 += __shfl_xor_sync(0xffffffffu, p0, 4);
        osm_update(m, d, acc, p0, a0);
    }

    float inv = 1.f / (d + 1e-16f);
    float4 bi = __ldg((const float4*)bias + lane);
    float4 v;
    v.x = acc.x * inv + bi.x; v.x = v.x > 0.f ? v.x : (__expf(v.x) - 1.f);
    v.y = acc.y * inv + bi.y; v.y = v.y > 0.f ? v.y : (__expf(v.y) - 1.f);
    v.z = acc.z * inv + bi.z; v.z = v.z > 0.f ? v.z : (__expf(v.z) - 1.f);
    v.w = acc.w * inv + bi.w; v.w = v.w > 0.f ? v.w : (__expf(v.w) - 1.f);
    *(float4*)(g_h + (size_t)n * 128 + 4 * lane) = v;
}

// ---------------- fused GATv2 per-node kernel, H=1 + pooling -----------------
__global__ void gat_node1_kernel(const float* __restrict__ att,
                                 const float* __restrict__ bias, int N) {
    int n = (blockIdx.x * blockDim.x + threadIdx.x) >> 5;
    int lane = threadIdx.x & 31;
    if (n >= N) return;
    int grp = lane >> 3, sl = lane & 7;

    float4 attv = __ldg((const float4*)att + sl);
    float4 xrv = *(const float4*)(g_xr + (size_t)n * 32 + 4 * sl);
    float m = -INFINITY, d = 0.f;
    float4 acc = make_float4(0.f, 0.f, 0.f, 0.f);

    int start = g_rowptr[n], end = g_rowptr[n + 1];
    for (int eb = start; eb < end; eb += 4) {
        int me = eb + grp;
        bool valid = me < end;
        int s = valid ? g_csrc[me] : g_csrc[eb];
        float4 a = *(const float4*)(g_xl + (size_t)s * 32 + 4 * sl);
        float p = edot4(a, xrv, attv);
        p += __shfl_xor_sync(0xffffffffu, p, 1);
        p += __shfl_xor_sync(0xffffffffu, p, 2);
        p += __shfl_xor_sync(0xffffffffu, p, 4);
        if (valid) osm_update(m, d, acc, p, a);
    }

    // merge the 4 group states (xor 8, then 16)
#pragma unroll
    for (int off = 8; off <= 16; off <<= 1) {
        float mo = __shfl_xor_sync(0xffffffffu, m, off);
        float do_ = __shfl_xor_sync(0xffffffffu, d, off);
        float4 ao;
        ao.x = __shfl_xor_sync(0xffffffffu, acc.x, off);
        ao.y = __shfl_xor_sync(0xffffffffu, acc.y, off);
        ao.z = __shfl_xor_sync(0xffffffffu, acc.z, off);
        ao.w = __shfl_xor_sync(0xffffffffu, acc.w, off);
        float nm = fmaxf(m, mo);
        float s1 = (m == nm) ? 1.f : __expf(m - nm);
        float s2 = (mo == nm) ? 1.f : __expf(mo - nm);
        d = d * s1 + do_ * s2;
        acc.x = acc.x * s1 + ao.x * s2;
        acc.y = acc.y * s1 + ao.y * s2;
        acc.z = acc.z * s1 + ao.z * s2;
        acc.w = acc.w * s1 + ao.w * s2;
        m = nm;
    }

    if (grp == 0) {
        float inv = 1.f / (d + 1e-16f);
        float4 bi = __ldg((const float4*)bias + sl);
        float4 v;
        v.x = acc.x * inv + bi.x; v.x = v.x > 0.f ? v.x : (__expf(v.x) - 1.f);
        v.y = acc.y * inv + bi.y; v.y = v.y > 0.f ? v.y : (__expf(v.y) - 1.f);
        v.z = acc.z * inv + bi.z; v.z = v.z > 0.f ? v.z : (__expf(v.z) - 1.f);
        v.w = acc.w * inv + bi.w; v.w = v.w > 0.f ? v.w : (__expf(v.w) - 1.f);
        int b = g_batch[n];
        atomicAdd(&g_pool[b * 32 + 4 * sl + 0], v.x);
        atomicAdd(&g_pool[b * 32 + 4 * sl + 1], v.y);
        atomicAdd(&g_pool[b * 32 + 4 * sl + 2], v.z);
        atomicAdd(&g_pool[b * 32 + 4 * sl + 3], v.w);
        if (sl == 0) atomicAdd(&g_cnt[b], 1.f);
    }
}

// ---------------- pooling init + MLP head -----------------------------------
__global__ void pool_init_kernel(int B) {
    int i = blockIdx.x * blockDim.x + threadIdx.x;
    if (i < B * 32) g_pool[i] = 0.f;
    if (i < B) g_cnt[i] = 0.f;
}

__global__ void head_kernel(const float* __restrict__ meta,
                            const float* __restrict__ Wh1,
                            const float* __restrict__ bh1,
                            const float* __restrict__ Wh2,
                            const float* __restrict__ bh2,
                            float* __restrict__ out, int B) {
    int g = (blockIdx.x * blockDim.x + threadIdx.x) >> 5;
    int lane = threadIdx.x & 31;
    if (g >= B) return;
    float c = g_cnt[g];
    if (c < 1.f) c = 1.f;
    float inv = 1.f / c;
    float acc = bh1[lane];
    for (int k = 0; k < 32; k++)
        acc += g_pool[g * 32 + k] * inv * Wh1[k * 32 + lane];
    for (int k = 0; k < 12; k++)
        acc += meta[g * 12 + k] * Wh1[(32 + k) * 32 + lane];
    acc = acc > 0.f ? acc : 0.f;
    float r = acc * Wh2[lane];
#pragma unroll
    for (int off = 16; off; off >>= 1)
        r += __shfl_xor_sync(0xffffffffu, r, off);
    if (lane == 0) out[g] = r + bh2[0];
}

// ---------------- host ------------------------------------------------------
extern "C" void kernel_launch(void* const* d_in, const int* in_sizes, int n_in,
                              void* d_out, int out_size) {
    const float* x     = (const float*)d_in[0];
    const void*  ei    = d_in[1];
    const void*  batch = d_in[2];
    const float* meta  = (const float*)d_in[3];

    const float *Wl[3], *bl[3], *Wr[3], *br[3], *att[3], *bo[3];
    for (int l = 0; l < 3; l++) {
        int base = 4 + 6 * l;
        Wl[l]  = (const float*)d_in[base + 0];
        bl[l]  = (const float*)d_in[base + 1];
        Wr[l]  = (const float*)d_in[base + 2];
        br[l]  = (const float*)d_in[base + 3];
        att[l] = (const float*)d_in[base + 4];
        bo[l]  = (const float*)d_in[base + 5];
    }
    const float* Wh1 = (const float*)d_in[22];
    const float* bh1 = (const float*)d_in[23];
    const float* Wh2 = (const float*)d_in[24];
    const float* bh2 = (const float*)d_in[25];

    int N = in_sizes[0] / 128;
    int E = in_sizes[1] / 2;
    int ET = E + N;
    int B = in_sizes[3] / 12;
    float* out = (float*)d_out;

    float *p_xl, *p_xr, *p_h;
    cudaGetSymbolAddress((void**)&p_xl, g_xl);
    cudaGetSymbolAddress((void**)&p_xr, g_xr);
    cudaGetSymbolAddress((void**)&p_h, g_h);

    int g8 = (N + 7) / 8;
    int g64 = (N + 63) / 64;
    int node_blocks = (N * 32 + 255) / 256;
    int pack128_blocks = (2 * 32 * 128 + 255) / 256;
    int pack32_blocks = (2 * 32 * 32 + 255) / 256;

    // ---- prolog; gemm128_dual is launch #4 (the ncu capture slot)
    detect_kernel<<<1, 256>>>(ei);
    pack_w_kernel<<<pack128_blocks, 256>>>(Wl[0], Wr[0], 128);
    zero_deg_kernel<<<(N + 255) / 256, 256>>>(N);
    gemm128_dual_kernel<<<g8, 64>>>(x, bl[0], br[0], p_xl, p_xr, N);
    convert_kernel<<<(ET + 255) / 256, 256>>>(ei, batch, E, N);

    // ---- CSR build (once; graph shared by all layers)
    int nb = (N + SCAN_BLK - 1) / SCAN_BLK;
    scan1_kernel<<<nb, SCAN_BLK>>>(N);
    scan2_kernel<<<1, SCAN_BLK>>>(nb);
    scan3_kernel<<<(N + 255) / 256, 256>>>(N);
    scatter_kernel<<<(ET + 255) / 256, 256>>>(ET);
    pool_init_kernel<<<(B * 32 + 255) / 256, 256>>>(B);

    // ---- layer 0 attention
    gat_node4_kernel<<<node_blocks, 256>>>(att[0], bo[0], N);

    // ---- layer 1
    pack_w_kernel<<<pack128_blocks, 256>>>(Wl[1], Wr[1], 128);
    gemm128_dual_kernel<<<g8, 64>>>(p_h, bl[1], br[1], p_xl, p_xr, N);
    gat_node4_kernel<<<node_blocks, 256>>>(att[1], bo[1], N);

    // ---- layer 2: H=1, DOUT=32, pool fused into epilogue
    pack_w_kernel<<<pack32_blocks, 256>>>(Wl[2], Wr[2], 32);
    gemm32_dual_kernel<<<g64, 128>>>(p_h, bl[2], br[2], p_xl, p_xr, N);
    gat_node1_kernel<<<node_blocks, 256>>>(att[2], bo[2], N);

    // ---- MLP head
    head_kernel<<<(B * 32 + 255) / 256, 256>>>(meta, Wh1, bh1, Wh2, bh2, out, B);
}